// round 3
// baseline (speedup 1.0000x reference)
#include <cuda_runtime.h>
#include <math.h>

#define T_STEPS 512
#define BATCH   128
#define IN_DIM  64
#define HID     1024
#define OUT_DIM 64
#define GATES   (3 * HID)
#define MROWS   (T_STEPS * BATCH)   // 65536
#define NBLK    128
#define NTHR    256
#define KCH     64
#define NCH     (HID / KCH)         // 16

typedef unsigned long long u64;

// Persistent scratch (device globals -- no allocation in kernel_launch).
__device__ float g_gi[(size_t)MROWS * GATES];  // input-side gates (reused by both layers)
__device__ float g_h1[(size_t)MROWS * HID];    // layer0 output, then overwritten with layer1 output
__device__ float g_hT[2][HID * BATCH];         // double-buffered hidden state, TRANSPOSED [H][B]
__device__ volatile unsigned g_bar_gen;
__device__ unsigned g_bar_cnt;

// ---------- f32x2 / async helpers ----------
__device__ __forceinline__ void fma2(u64 &d, u64 a, u64 b) {
    asm("fma.rn.f32x2 %0, %1, %2, %0;" : "+l"(d) : "l"(a), "l"(b));
}
__device__ __forceinline__ u64 dup2(float x) {
    u64 r; asm("mov.b64 %0, {%1, %1};" : "=l"(r) : "f"(x)); return r;
}
__device__ __forceinline__ float2 unpk(u64 v) {
    float2 r; asm("mov.b64 {%0, %1}, %2;" : "=f"(r.x), "=f"(r.y) : "l"(v)); return r;
}
__device__ __forceinline__ float4 ldcg_f32x4(const void* p) {
    float4 v;
    asm volatile("ld.global.cg.v4.f32 {%0, %1, %2, %3}, [%4];"
                 : "=f"(v.x), "=f"(v.y), "=f"(v.z), "=f"(v.w) : "l"(p));
    return v;
}
__device__ __forceinline__ float ldcg_f32(const void* p) {
    float v;
    asm volatile("ld.global.cg.f32 %0, [%1];" : "=f"(v) : "l"(p));
    return v;
}
__device__ __forceinline__ void cp16(unsigned d, const void* s) {
    asm volatile("cp.async.cg.shared.global [%0], [%1], 16;" :: "r"(d), "l"(s));
}

__device__ __forceinline__ void grid_bar() {
    __threadfence();
    __syncthreads();
    if (threadIdx.x == 0) {
        unsigned gen = g_bar_gen;
        if (atomicAdd(&g_bar_cnt, 1u) == (unsigned)(NBLK - 1)) {
            g_bar_cnt = 0u;
            __threadfence();
            g_bar_gen = gen + 1u;
        } else {
            while (g_bar_gen == gen) { }
        }
        __threadfence();
    }
    __syncthreads();
}

// ============================================================================
// Recurrence with input-side gates precomputed in g_gi.
// Block owns 8 hidden units. r/z weights (duplicated for f32x2) + scalar n
// weights live persistently in smem; h_prev activations are cp.async
// double-buffered into smem per 64-k chunk. k-loop: LDS + FFMA2 only.
// ============================================================================
__global__ void __launch_bounds__(NTHR, 1)
gru_rec(const float* __restrict__ w_hh, const float* __restrict__ b_ih,
        const float* __restrict__ b_hh)
{
    extern __shared__ float smem[];
    float* sWrz = smem;                 // [HID][8u][4] = {wr,wr,wz,wz}  128 KB
    float* sWn  = smem + HID * 32;      // [HID][8u]                      32 KB
    float* sAct = smem + HID * 40;      // [2][KCH][128]                  64 KB

    const int tid  = threadIdx.x;
    const int bid  = blockIdx.x;
    const int j0   = bid * 8;
    const int jl   = tid & 7;
    const int j    = j0 + jl;
    const int brow = (tid >> 3) << 2;  // batch base, 0..124

    const unsigned act_smem = (unsigned)__cvta_generic_to_shared(sAct);
    const int cp_row = tid >> 2;          // k row within chunk (0..63)
    const int cp_col = (tid & 3) * 32;    // batch offset (floats)

    // fill persistent weight tile (coalesced over k)
    for (int idx = tid; idx < HID * 8; idx += NTHR) {
        int u = idx >> 10;
        int k = idx & 1023;
        int row = j0 + u;
        float wr = w_hh[(size_t)row * HID + k];
        float wz = w_hh[(size_t)(HID + row) * HID + k];
        float wn = w_hh[(size_t)(2 * HID + row) * HID + k];
        float* p = sWrz + k * 32 + u * 4;
        p[0] = wr; p[1] = wr; p[2] = wz; p[3] = wz;
        sWn[k * 8 + u] = wn;
    }

    const float br_b  = b_ih[j] + b_hh[j];
    const float bz_b  = b_ih[HID + j] + b_hh[HID + j];
    const float bin_b = b_ih[2 * HID + j];
    const float bhn_b = b_hh[2 * HID + j];

    // h0 = 0
    for (int idx = bid * NTHR + tid; idx < HID * BATCH; idx += NBLK * NTHR)
        g_hT[0][idx] = 0.0f;

    grid_bar();

    for (int t = 0; t < T_STEPS; ++t) {
        const float* hT  = g_hT[t & 1];
        float*       hTn = g_hT[(t + 1) & 1];

        // issue chunk 0
        {
            const float* src = hT + (size_t)cp_row * BATCH + cp_col;
            unsigned dst = act_smem + (unsigned)((cp_row * 128 + cp_col) * 4);
            #pragma unroll
            for (int i = 0; i < 8; ++i) cp16(dst + i * 16, src + i * 4);
            asm volatile("cp.async.commit_group;");
        }

        // prefetch gi + h_prev for the epilogue (consumed after k-loop)
        const float* gi = g_gi + (size_t)t * BATCH * GATES;
        float gir[4], giz[4], gin[4];
        #pragma unroll
        for (int i = 0; i < 4; ++i) {
            const float* gp = gi + (size_t)(brow + i) * GATES + j;
            gir[i] = ldcg_f32(gp);
            giz[i] = ldcg_f32(gp + HID);
            gin[i] = ldcg_f32(gp + 2 * HID);
        }
        float4 hp = ldcg_f32x4(hT + (size_t)j * BATCH + brow);

        u64 ar0 = 0, ar1 = 0, az0 = 0, az1 = 0, an0 = 0, an1 = 0;

        #pragma unroll 1
        for (int c = 0; c < NCH; ++c) {
            if (c + 1 < NCH) {
                const float* src = hT + (size_t)((c + 1) * KCH + cp_row) * BATCH + cp_col;
                unsigned dst = act_smem +
                    (unsigned)((((c + 1) & 1) * KCH * 128 + cp_row * 128 + cp_col) * 4);
                #pragma unroll
                for (int i = 0; i < 8; ++i) cp16(dst + i * 16, src + i * 4);
                asm volatile("cp.async.commit_group;");
                asm volatile("cp.async.wait_group 1;");
            } else {
                asm volatile("cp.async.wait_group 0;");
            }
            __syncthreads();   // chunk c visible to all

            const float* ab = sAct + (c & 1) * (KCH * 128) + brow;
            const int kg0 = c * KCH;
            #pragma unroll 8
            for (int kk = 0; kk < KCH; ++kk) {
                ulonglong2 av  = *(const ulonglong2*)(ab + kk * 128);
                ulonglong2 wrz = *(const ulonglong2*)(sWrz + (kg0 + kk) * 32 + jl * 4);
                u64 wn = dup2(sWn[(kg0 + kk) * 8 + jl]);
                fma2(ar0, av.x, wrz.x); fma2(ar1, av.y, wrz.x);
                fma2(az0, av.x, wrz.y); fma2(az1, av.y, wrz.y);
                fma2(an0, av.x, wn);    fma2(an1, av.y, wn);
            }
            __syncthreads();   // chunk c fully consumed (its buffer is refilled next iter)
        }

        float2 r01 = unpk(ar0), r23 = unpk(ar1);
        float2 z01 = unpk(az0), z23 = unpk(az1);
        float2 n01 = unpk(an0), n23 = unpk(an1);
        float rr[4]  = {r01.x, r01.y, r23.x, r23.y};
        float zz[4]  = {z01.x, z01.y, z23.x, z23.y};
        float nn[4]  = {n01.x, n01.y, n23.x, n23.y};
        float hpv[4] = {hp.x, hp.y, hp.z, hp.w};
        float hv[4];
        #pragma unroll
        for (int i = 0; i < 4; ++i) {
            float rg = 1.0f / (1.0f + expf(-(gir[i] + rr[i] + br_b)));
            float zg = 1.0f / (1.0f + expf(-(giz[i] + zz[i] + bz_b)));
            float ng = tanhf(gin[i] + bin_b + rg * (nn[i] + bhn_b));
            hv[i] = (1.0f - zg) * ng + zg * hpv[i];
        }

        *(float4*)(hTn + (size_t)j * BATCH + brow) = make_float4(hv[0], hv[1], hv[2], hv[3]);
        // layer output in [T][B][H] (layer0: feeds gi1 GEMM; layer1: feeds out_linear)
        float* o = g_h1 + (size_t)t * BATCH * HID + j;
        #pragma unroll
        for (int i = 0; i < 4; ++i) o[(size_t)(brow + i) * HID] = hv[i];

        grid_bar();
    }
}

// ============================================================================
// C[m][n] = sum_k A[m][k] * B[n][k]   (both k-contiguous), f32x2 inner.
// 128x128 tile / block, 256 threads, thread tile 8x8, KC=16.
// ============================================================================
#define GKC 16
__global__ void __launch_bounds__(256)
gemm_tn_f32x2(const float* __restrict__ A, const float* __restrict__ B,
              float* __restrict__ C, int M, int N, int K)
{
    __shared__ float sA[GKC][132];
    __shared__ float sB[GKC][132];
    const int tid = threadIdx.x;
    const int m0  = blockIdx.y * 128;
    const int n0  = blockIdx.x * 128;
    const int ty  = tid >> 4, tx = tid & 15;

    const int sr = tid >> 1;
    const int sk = (tid & 1) * 8;

    u64 acc[4][8];
    #pragma unroll
    for (int p = 0; p < 4; ++p)
        #pragma unroll
        for (int c = 0; c < 8; ++c) acc[p][c] = 0ull;

    const float* Ag = A + (size_t)(m0 + sr) * K + sk;
    const float* Bg = B + (size_t)(n0 + sr) * K + sk;

    float4 a0 = ldcg_f32x4(Ag);
    float4 a1 = ldcg_f32x4(Ag + 4);
    float4 b0 = ldcg_f32x4(Bg);
    float4 b1 = ldcg_f32x4(Bg + 4);

    for (int kc = 0; kc < K; kc += GKC) {
        sA[sk + 0][sr] = a0.x; sA[sk + 1][sr] = a0.y;
        sA[sk + 2][sr] = a0.z; sA[sk + 3][sr] = a0.w;
        sA[sk + 4][sr] = a1.x; sA[sk + 5][sr] = a1.y;
        sA[sk + 6][sr] = a1.z; sA[sk + 7][sr] = a1.w;
        sB[sk + 0][sr] = b0.x; sB[sk + 1][sr] = b0.y;
        sB[sk + 2][sr] = b0.z; sB[sk + 3][sr] = b0.w;
        sB[sk + 4][sr] = b1.x; sB[sk + 5][sr] = b1.y;
        sB[sk + 6][sr] = b1.z; sB[sk + 7][sr] = b1.w;
        if (kc + GKC < K) {
            Ag += GKC; Bg += GKC;
            a0 = ldcg_f32x4(Ag);
            a1 = ldcg_f32x4(Ag + 4);
            b0 = ldcg_f32x4(Bg);
            b1 = ldcg_f32x4(Bg + 4);
        }
        __syncthreads();

        #pragma unroll
        for (int kk = 0; kk < GKC; ++kk) {
            ulonglong2 aa = *(const ulonglong2*)(&sA[kk][ty * 8]);
            ulonglong2 ab = *(const ulonglong2*)(&sA[kk][ty * 8 + 4]);
            float4 bv0 = *(const float4*)(&sB[kk][tx * 8]);
            float4 bv1 = *(const float4*)(&sB[kk][tx * 8 + 4]);
            float bs[8] = {bv0.x, bv0.y, bv0.z, bv0.w, bv1.x, bv1.y, bv1.z, bv1.w};
            #pragma unroll
            for (int c = 0; c < 8; ++c) {
                u64 bd = dup2(bs[c]);
                fma2(acc[0][c], aa.x, bd);
                fma2(acc[1][c], aa.y, bd);
                fma2(acc[2][c], ab.x, bd);
                fma2(acc[3][c], ab.y, bd);
            }
        }
        __syncthreads();
    }

    #pragma unroll
    for (int p = 0; p < 4; ++p) {
        float2 v[8];
        #pragma unroll
        for (int c = 0; c < 8; ++c) v[c] = unpk(acc[p][c]);
        int row0 = m0 + ty * 8 + p * 2;
        float* c0 = C + (size_t)row0 * N + n0 + tx * 8;
        float* c1 = c0 + N;
        *(float4*)(c0)     = make_float4(v[0].x, v[1].x, v[2].x, v[3].x);
        *(float4*)(c0 + 4) = make_float4(v[4].x, v[5].x, v[6].x, v[7].x);
        *(float4*)(c1)     = make_float4(v[0].y, v[1].y, v[2].y, v[3].y);
        *(float4*)(c1 + 4) = make_float4(v[4].y, v[5].y, v[6].y, v[7].y);
    }
}

// ============================================================================
// out[t,b,o] = h2[t,b,:] . w_lin[o,:] + b_lin[o] (h2 lives in g_h1)
// ============================================================================
__global__ void __launch_bounds__(256)
out_linear(const float* __restrict__ w_lin, const float* __restrict__ b_lin,
           float* __restrict__ out)
{
    __shared__ float sA[16][68];
    __shared__ float sB[16][68];
    const int tid = threadIdx.x;
    const size_t rb = (size_t)blockIdx.x * 64;
    const int ty = tid >> 4;
    const int tx = tid & 15;

    const int li   = tid * 4;
    const int srow = li >> 4;
    const int skk  = li & 15;

    float acc[4][4] = {};

    for (int kc = 0; kc < HID; kc += 16) {
        __syncthreads();
        float4 va = ldcg_f32x4(g_h1 + (rb + srow) * HID + kc + skk);
        sA[skk + 0][srow] = va.x; sA[skk + 1][srow] = va.y;
        sA[skk + 2][srow] = va.z; sA[skk + 3][srow] = va.w;
        float4 vb = *(const float4*)(w_lin + (size_t)srow * HID + kc + skk);
        sB[skk + 0][srow] = vb.x; sB[skk + 1][srow] = vb.y;
        sB[skk + 2][srow] = vb.z; sB[skk + 3][srow] = vb.w;
        __syncthreads();
        #pragma unroll
        for (int kk = 0; kk < 16; ++kk) {
            float4 a = *(const float4*)&sA[kk][ty * 4];
            float4 b = *(const float4*)&sB[kk][tx * 4];
            acc[0][0] = fmaf(a.x, b.x, acc[0][0]); acc[0][1] = fmaf(a.x, b.y, acc[0][1]);
            acc[0][2] = fmaf(a.x, b.z, acc[0][2]); acc[0][3] = fmaf(a.x, b.w, acc[0][3]);
            acc[1][0] = fmaf(a.y, b.x, acc[1][0]); acc[1][1] = fmaf(a.y, b.y, acc[1][1]);
            acc[1][2] = fmaf(a.y, b.z, acc[1][2]); acc[1][3] = fmaf(a.y, b.w, acc[1][3]);
            acc[2][0] = fmaf(a.z, b.x, acc[2][0]); acc[2][1] = fmaf(a.z, b.y, acc[2][1]);
            acc[2][2] = fmaf(a.z, b.z, acc[2][2]); acc[2][3] = fmaf(a.z, b.w, acc[2][3]);
            acc[3][0] = fmaf(a.w, b.x, acc[3][0]); acc[3][1] = fmaf(a.w, b.y, acc[3][1]);
            acc[3][2] = fmaf(a.w, b.z, acc[3][2]); acc[3][3] = fmaf(a.w, b.w, acc[3][3]);
        }
    }

    #pragma unroll
    for (int i = 0; i < 4; ++i) {
        float4 o4;
        o4.x = acc[i][0] + b_lin[tx * 4 + 0];
        o4.y = acc[i][1] + b_lin[tx * 4 + 1];
        o4.z = acc[i][2] + b_lin[tx * 4 + 2];
        o4.w = acc[i][3] + b_lin[tx * 4 + 3];
        *(float4*)(out + (rb + ty * 4 + i) * OUT_DIM + tx * 4) = o4;
    }
}

extern "C" void kernel_launch(void* const* d_in, const int* in_sizes, int n_in,
                              void* d_out, int out_size)
{
    const float* x     = (const float*)d_in[0];
    const float* w_ih0 = (const float*)d_in[1];
    const float* w_hh0 = (const float*)d_in[2];
    const float* b_ih0 = (const float*)d_in[3];
    const float* b_hh0 = (const float*)d_in[4];
    const float* w_ih1 = (const float*)d_in[5];
    const float* w_hh1 = (const float*)d_in[6];
    const float* b_ih1 = (const float*)d_in[7];
    const float* b_hh1 = (const float*)d_in[8];
    const float* w_lin = (const float*)d_in[9];
    const float* b_lin = (const float*)d_in[10];
    float* out = (float*)d_out;
    (void)in_sizes; (void)n_in; (void)out_size;

    float *gi_ptr, *h1_ptr;
    cudaGetSymbolAddress((void**)&gi_ptr, g_gi);
    cudaGetSymbolAddress((void**)&h1_ptr, g_h1);

    const int rec_smem = (HID * 40 + 2 * KCH * 128) * 4;  // 229,376 B
    cudaFuncSetAttribute(gru_rec, cudaFuncAttributeMaxDynamicSharedMemorySize, rec_smem);

    dim3 ggrid(GATES / 128, MROWS / 128);   // (24, 512)

    // layer 0: input-side gates (K=64), then recurrence
    gemm_tn_f32x2<<<ggrid, 256>>>(x, w_ih0, gi_ptr, MROWS, GATES, IN_DIM);
    gru_rec<<<NBLK, NTHR, rec_smem>>>(w_hh0, b_ih0, b_hh0);

    // layer 1: input-side gates from h1 (K=1024), then recurrence
    gemm_tn_f32x2<<<ggrid, 256>>>(h1_ptr, w_ih1, gi_ptr, MROWS, GATES, HID);
    gru_rec<<<NBLK, NTHR, rec_smem>>>(w_hh1, b_ih1, b_hh1);

    // time-distributed linear on h2 (in g_h1)
    out_linear<<<(MROWS) / 64, 256>>>(w_lin, b_lin, out);
}

// round 4
// speedup vs baseline: 1.1524x; 1.1524x over previous
#include <cuda_runtime.h>
#include <math.h>

#define T_STEPS 512
#define BATCH   128
#define IN_DIM  64
#define HID     1024
#define OUT_DIM 64
#define GATES   (3 * HID)
#define MROWS   (T_STEPS * BATCH)   // 65536
#define NBLK    128
#define NTHR    512                 // recurrence kernel threads
#define KCH     32                  // k rows per half per staging iteration
#define NIT     16                  // (HID/2)/KCH

typedef unsigned long long u64;

// Persistent scratch (device globals -- no allocation in kernel_launch).
__device__ float g_gi[(size_t)MROWS * GATES];  // input-side gates (reused by both layers)
__device__ float g_h1[(size_t)MROWS * HID];    // layer0 out, then overwritten by layer1 out
__device__ float g_hT[2][HID * BATCH];         // double-buffered hidden state, TRANSPOSED [H][B]
__device__ volatile unsigned g_bar_gen;
__device__ unsigned g_bar_cnt;

// ---------- f32x2 / async helpers ----------
__device__ __forceinline__ void fma2(u64 &d, u64 a, u64 b) {
    asm("fma.rn.f32x2 %0, %1, %2, %0;" : "+l"(d) : "l"(a), "l"(b));
}
__device__ __forceinline__ void add2(u64 &d, u64 a) {
    asm("add.rn.f32x2 %0, %0, %1;" : "+l"(d) : "l"(a));
}
__device__ __forceinline__ u64 dup2(float x) {
    u64 r; asm("mov.b64 %0, {%1, %1};" : "=l"(r) : "f"(x)); return r;
}
__device__ __forceinline__ float2 unpk(u64 v) {
    float2 r; asm("mov.b64 {%0, %1}, %2;" : "=f"(r.x), "=f"(r.y) : "l"(v)); return r;
}
__device__ __forceinline__ float4 ldcg_f32x4(const void* p) {
    float4 v;
    asm volatile("ld.global.cg.v4.f32 {%0, %1, %2, %3}, [%4];"
                 : "=f"(v.x), "=f"(v.y), "=f"(v.z), "=f"(v.w) : "l"(p));
    return v;
}
__device__ __forceinline__ float ldcg_f32(const void* p) {
    float v;
    asm volatile("ld.global.cg.f32 %0, [%1];" : "=f"(v) : "l"(p));
    return v;
}
__device__ __forceinline__ void cp16(unsigned d, const void* s) {
    asm volatile("cp.async.cg.shared.global [%0], [%1], 16;" :: "r"(d), "l"(s));
}

__device__ __forceinline__ void grid_bar() {
    __threadfence();
    __syncthreads();
    if (threadIdx.x == 0) {
        unsigned gen = g_bar_gen;
        if (atomicAdd(&g_bar_cnt, 1u) == (unsigned)(NBLK - 1)) {
            g_bar_cnt = 0u;
            __threadfence();
            g_bar_gen = gen + 1u;
        } else {
            while (g_bar_gen == gen) { }
        }
        __threadfence();
    }
    __syncthreads();
}

// ============================================================================
// Recurrence, input gates precomputed in g_gi. Block owns 8 hidden units.
// 512 threads: tid<256 accumulate k in [0,512), tid>=256 k in [512,1024);
// partial sums merged through smem once per step. Weights persistent in smem;
// activations cp.async double-buffered (32 k-rows per half per iteration).
// ============================================================================
__global__ void __launch_bounds__(NTHR, 1)
gru_rec(const float* __restrict__ w_hh, const float* __restrict__ b_ih,
        const float* __restrict__ b_hh)
{
    extern __shared__ float smem[];
    float* sWrz = smem;               // [HID][8u][4] = {wr,wr,wz,wz}  128 KB
    float* sWn  = smem + HID * 32;    // [HID][8u]                      32 KB
    float* sAct = smem + HID * 40;    // [2 buf][2 half][KCH][128]      64 KB

    const int tid   = threadIdx.x;
    const int bid   = blockIdx.x;
    const int j0    = bid * 8;
    const int jl    = tid & 7;
    const int j     = j0 + jl;
    const int brow  = ((tid >> 3) & 31) << 2;  // batch base 0..124
    const int kh    = tid >> 8;                // k half: 0 or 1
    const int kbase = kh << 9;                 // 0 or 512
    const bool lo   = (tid < 256);

    const unsigned act_smem = (unsigned)__cvta_generic_to_shared(sAct);
    // staging map: thread covers 16 consecutive floats of the 8192-float unit
    const int sf     = tid * 16;
    const int s_half = sf >> 12;          // 0 for tid<256, 1 for tid>=256
    const int s_kk   = (sf & 4095) >> 7;  // row within chunk
    const int s_col  = sf & 127;          // batch column

    // fill persistent weight tile (coalesced over k)
    for (int idx = tid; idx < HID * 8; idx += NTHR) {
        int u = idx >> 10;
        int k = idx & 1023;
        int row = j0 + u;
        float wr = w_hh[(size_t)row * HID + k];
        float wz = w_hh[(size_t)(HID + row) * HID + k];
        float wn = w_hh[(size_t)(2 * HID + row) * HID + k];
        float* p = sWrz + k * 32 + u * 4;
        p[0] = wr; p[1] = wr; p[2] = wz; p[3] = wz;
        sWn[k * 8 + u] = wn;
    }

    const float br_b  = b_ih[j] + b_hh[j];
    const float bz_b  = b_ih[HID + j] + b_hh[HID + j];
    const float bin_b = b_ih[2 * HID + j];
    const float bhn_b = b_hh[2 * HID + j];

    // h0 = 0
    for (int idx = bid * NTHR + tid; idx < HID * BATCH; idx += NBLK * NTHR)
        g_hT[0][idx] = 0.0f;

    grid_bar();

    for (int t = 0; t < T_STEPS; ++t) {
        const float* hT  = g_hT[t & 1];
        float*       hTn = g_hT[(t + 1) & 1];

        // stage iteration 0 (k rows [0,32) and [512,544))
        {
            const float* src = hT + (size_t)(s_half * 512 + s_kk) * BATCH + s_col;
            unsigned dst = act_smem + (unsigned)(sf * 4);
            #pragma unroll
            for (int i = 0; i < 4; ++i) cp16(dst + i * 16, src + i * 4);
            asm volatile("cp.async.commit_group;");
        }

        // prefetch epilogue operands (lo half only; consumed after k-loop)
        float gir[4], giz[4], gin[4];
        float4 hp = make_float4(0.f, 0.f, 0.f, 0.f);
        if (lo) {
            const float* gi = g_gi + (size_t)t * BATCH * GATES;
            #pragma unroll
            for (int i = 0; i < 4; ++i) {
                const float* gp = gi + (size_t)(brow + i) * GATES + j;
                gir[i] = ldcg_f32(gp);
                giz[i] = ldcg_f32(gp + HID);
                gin[i] = ldcg_f32(gp + 2 * HID);
            }
            hp = ldcg_f32x4(hT + (size_t)j * BATCH + brow);
        }

        u64 ar = 0, ar1 = 0, az = 0, az1 = 0, an = 0, an1 = 0;

        #pragma unroll 1
        for (int c = 0; c < NIT; ++c) {
            if (c + 1 < NIT) {
                const float* src = hT +
                    (size_t)(s_half * 512 + (c + 1) * KCH + s_kk) * BATCH + s_col;
                unsigned dst = act_smem +
                    (unsigned)((((c + 1) & 1) * 8192 + sf) * 4);
                #pragma unroll
                for (int i = 0; i < 4; ++i) cp16(dst + i * 16, src + i * 4);
                asm volatile("cp.async.commit_group;");
                asm volatile("cp.async.wait_group 1;");
            } else {
                asm volatile("cp.async.wait_group 0;");
            }
            __syncthreads();   // chunk c visible to all

            const float* ab  = sAct + (c & 1) * 8192 + kh * 4096 + brow;
            const float* wp  = sWrz + (size_t)(kbase + c * KCH) * 32 + jl * 4;
            const float* wnp = sWn + (size_t)(kbase + c * KCH) * 8 + jl;
            #pragma unroll 8
            for (int kk = 0; kk < KCH; ++kk) {
                ulonglong2 av  = *(const ulonglong2*)(ab + kk * 128);
                ulonglong2 wrz = *(const ulonglong2*)(wp + kk * 32);
                u64 wn = dup2(wnp[kk * 8]);
                fma2(ar, av.x, wrz.x); fma2(ar1, av.y, wrz.x);
                fma2(az, av.x, wrz.y); fma2(az1, av.y, wrz.y);
                fma2(an, av.x, wn);    fma2(an1, av.y, wn);
            }
            __syncthreads();   // chunk c consumed (buffer refilled next iter)
        }

        // ---- merge k-halves through smem ----
        u64* red = (u64*)sAct;   // 256 * 6 u64 = 12 KB (act buffers idle here)
        if (!lo) {
            u64* r = red + (size_t)(tid - 256) * 6;
            r[0] = ar;  r[1] = ar1;
            r[2] = az;  r[3] = az1;
            r[4] = an;  r[5] = an1;
        }
        __syncthreads();

        if (lo) {
            const u64* r = red + (size_t)tid * 6;
            add2(ar, r[0]);  add2(ar1, r[1]);
            add2(az, r[2]);  add2(az1, r[3]);
            add2(an, r[4]);  add2(an1, r[5]);

            float2 r01 = unpk(ar), r23 = unpk(ar1);
            float2 z01 = unpk(az), z23 = unpk(az1);
            float2 n01 = unpk(an), n23 = unpk(an1);
            float rr[4]  = {r01.x, r01.y, r23.x, r23.y};
            float zz[4]  = {z01.x, z01.y, z23.x, z23.y};
            float nn[4]  = {n01.x, n01.y, n23.x, n23.y};
            float hpv[4] = {hp.x, hp.y, hp.z, hp.w};
            float hv[4];
            #pragma unroll
            for (int i = 0; i < 4; ++i) {
                float rg = 1.0f / (1.0f + expf(-(gir[i] + rr[i] + br_b)));
                float zg = 1.0f / (1.0f + expf(-(giz[i] + zz[i] + bz_b)));
                float ng = tanhf(gin[i] + bin_b + rg * (nn[i] + bhn_b));
                hv[i] = (1.0f - zg) * ng + zg * hpv[i];
            }

            *(float4*)(hTn + (size_t)j * BATCH + brow) =
                make_float4(hv[0], hv[1], hv[2], hv[3]);
            float* o = g_h1 + (size_t)t * BATCH * HID + j;
            #pragma unroll
            for (int i = 0; i < 4; ++i) o[(size_t)(brow + i) * HID] = hv[i];
        }

        grid_bar();
    }
}

// ============================================================================
// C[m][n] = sum_k A[m][k] * B[n][k]   (both k-contiguous), f32x2 inner.
// 128x128 tile / block, 256 threads, thread tile 8x8, KC=16.
// ============================================================================
#define GKC 16
__global__ void __launch_bounds__(256)
gemm_tn_f32x2(const float* __restrict__ A, const float* __restrict__ B,
              float* __restrict__ C, int M, int N, int K)
{
    __shared__ float sA[GKC][132];
    __shared__ float sB[GKC][132];
    const int tid = threadIdx.x;
    const int m0  = blockIdx.y * 128;
    const int n0  = blockIdx.x * 128;
    const int ty  = tid >> 4, tx = tid & 15;

    const int sr = tid >> 1;
    const int sk = (tid & 1) * 8;

    u64 acc[4][8];
    #pragma unroll
    for (int p = 0; p < 4; ++p)
        #pragma unroll
        for (int c = 0; c < 8; ++c) acc[p][c] = 0ull;

    const float* Ag = A + (size_t)(m0 + sr) * K + sk;
    const float* Bg = B + (size_t)(n0 + sr) * K + sk;

    float4 a0 = ldcg_f32x4(Ag);
    float4 a1 = ldcg_f32x4(Ag + 4);
    float4 b0 = ldcg_f32x4(Bg);
    float4 b1 = ldcg_f32x4(Bg + 4);

    for (int kc = 0; kc < K; kc += GKC) {
        sA[sk + 0][sr] = a0.x; sA[sk + 1][sr] = a0.y;
        sA[sk + 2][sr] = a0.z; sA[sk + 3][sr] = a0.w;
        sA[sk + 4][sr] = a1.x; sA[sk + 5][sr] = a1.y;
        sA[sk + 6][sr] = a1.z; sA[sk + 7][sr] = a1.w;
        sB[sk + 0][sr] = b0.x; sB[sk + 1][sr] = b0.y;
        sB[sk + 2][sr] = b0.z; sB[sk + 3][sr] = b0.w;
        sB[sk + 4][sr] = b1.x; sB[sk + 5][sr] = b1.y;
        sB[sk + 6][sr] = b1.z; sB[sk + 7][sr] = b1.w;
        if (kc + GKC < K) {
            Ag += GKC; Bg += GKC;
            a0 = ldcg_f32x4(Ag);
            a1 = ldcg_f32x4(Ag + 4);
            b0 = ldcg_f32x4(Bg);
            b1 = ldcg_f32x4(Bg + 4);
        }
        __syncthreads();

        #pragma unroll
        for (int kk = 0; kk < GKC; ++kk) {
            ulonglong2 aa = *(const ulonglong2*)(&sA[kk][ty * 8]);
            ulonglong2 ab = *(const ulonglong2*)(&sA[kk][ty * 8 + 4]);
            float4 bv0 = *(const float4*)(&sB[kk][tx * 8]);
            float4 bv1 = *(const float4*)(&sB[kk][tx * 8 + 4]);
            float bs[8] = {bv0.x, bv0.y, bv0.z, bv0.w, bv1.x, bv1.y, bv1.z, bv1.w};
            #pragma unroll
            for (int c = 0; c < 8; ++c) {
                u64 bd = dup2(bs[c]);
                fma2(acc[0][c], aa.x, bd);
                fma2(acc[1][c], aa.y, bd);
                fma2(acc[2][c], ab.x, bd);
                fma2(acc[3][c], ab.y, bd);
            }
        }
        __syncthreads();
    }

    #pragma unroll
    for (int p = 0; p < 4; ++p) {
        float2 v[8];
        #pragma unroll
        for (int c = 0; c < 8; ++c) v[c] = unpk(acc[p][c]);
        int row0 = m0 + ty * 8 + p * 2;
        float* c0 = C + (size_t)row0 * N + n0 + tx * 8;
        float* c1 = c0 + N;
        *(float4*)(c0)     = make_float4(v[0].x, v[1].x, v[2].x, v[3].x);
        *(float4*)(c0 + 4) = make_float4(v[4].x, v[5].x, v[6].x, v[7].x);
        *(float4*)(c1)     = make_float4(v[0].y, v[1].y, v[2].y, v[3].y);
        *(float4*)(c1 + 4) = make_float4(v[4].y, v[5].y, v[6].y, v[7].y);
    }
}

// ============================================================================
// out[t,b,o] = h2[t,b,:] . w_lin[o,:] + b_lin[o] (h2 lives in g_h1)
// ============================================================================
__global__ void __launch_bounds__(256)
out_linear(const float* __restrict__ w_lin, const float* __restrict__ b_lin,
           float* __restrict__ out)
{
    __shared__ float sA[16][68];
    __shared__ float sB[16][68];
    const int tid = threadIdx.x;
    const size_t rb = (size_t)blockIdx.x * 64;
    const int ty = tid >> 4;
    const int tx = tid & 15;

    const int li   = tid * 4;
    const int srow = li >> 4;
    const int skk  = li & 15;

    float acc[4][4] = {};

    for (int kc = 0; kc < HID; kc += 16) {
        __syncthreads();
        float4 va = ldcg_f32x4(g_h1 + (rb + srow) * HID + kc + skk);
        sA[skk + 0][srow] = va.x; sA[skk + 1][srow] = va.y;
        sA[skk + 2][srow] = va.z; sA[skk + 3][srow] = va.w;
        float4 vb = *(const float4*)(w_lin + (size_t)srow * HID + kc + skk);
        sB[skk + 0][srow] = vb.x; sB[skk + 1][srow] = vb.y;
        sB[skk + 2][srow] = vb.z; sB[skk + 3][srow] = vb.w;
        __syncthreads();
        #pragma unroll
        for (int kk = 0; kk < 16; ++kk) {
            float4 a = *(const float4*)&sA[kk][ty * 4];
            float4 b = *(const float4*)&sB[kk][tx * 4];
            acc[0][0] = fmaf(a.x, b.x, acc[0][0]); acc[0][1] = fmaf(a.x, b.y, acc[0][1]);
            acc[0][2] = fmaf(a.x, b.z, acc[0][2]); acc[0][3] = fmaf(a.x, b.w, acc[0][3]);
            acc[1][0] = fmaf(a.y, b.x, acc[1][0]); acc[1][1] = fmaf(a.y, b.y, acc[1][1]);
            acc[1][2] = fmaf(a.y, b.z, acc[1][2]); acc[1][3] = fmaf(a.y, b.w, acc[1][3]);
            acc[2][0] = fmaf(a.z, b.x, acc[2][0]); acc[2][1] = fmaf(a.z, b.y, acc[2][1]);
            acc[2][2] = fmaf(a.z, b.z, acc[2][2]); acc[2][3] = fmaf(a.z, b.w, acc[2][3]);
            acc[3][0] = fmaf(a.w, b.x, acc[3][0]); acc[3][1] = fmaf(a.w, b.y, acc[3][1]);
            acc[3][2] = fmaf(a.w, b.z, acc[3][2]); acc[3][3] = fmaf(a.w, b.w, acc[3][3]);
        }
    }

    #pragma unroll
    for (int i = 0; i < 4; ++i) {
        float4 o4;
        o4.x = acc[i][0] + b_lin[tx * 4 + 0];
        o4.y = acc[i][1] + b_lin[tx * 4 + 1];
        o4.z = acc[i][2] + b_lin[tx * 4 + 2];
        o4.w = acc[i][3] + b_lin[tx * 4 + 3];
        *(float4*)(out + (rb + ty * 4 + i) * OUT_DIM + tx * 4) = o4;
    }
}

extern "C" void kernel_launch(void* const* d_in, const int* in_sizes, int n_in,
                              void* d_out, int out_size)
{
    const float* x     = (const float*)d_in[0];
    const float* w_ih0 = (const float*)d_in[1];
    const float* w_hh0 = (const float*)d_in[2];
    const float* b_ih0 = (const float*)d_in[3];
    const float* b_hh0 = (const float*)d_in[4];
    const float* w_ih1 = (const float*)d_in[5];
    const float* w_hh1 = (const float*)d_in[6];
    const float* b_ih1 = (const float*)d_in[7];
    const float* b_hh1 = (const float*)d_in[8];
    const float* w_lin = (const float*)d_in[9];
    const float* b_lin = (const float*)d_in[10];
    float* out = (float*)d_out;
    (void)in_sizes; (void)n_in; (void)out_size;

    float *gi_ptr, *h1_ptr;
    cudaGetSymbolAddress((void**)&gi_ptr, g_gi);
    cudaGetSymbolAddress((void**)&h1_ptr, g_h1);

    const int rec_smem = (HID * 40 + 2 * 8192) * 4;  // 229,376 B
    cudaFuncSetAttribute(gru_rec, cudaFuncAttributeMaxDynamicSharedMemorySize, rec_smem);

    dim3 ggrid(GATES / 128, MROWS / 128);   // (24, 512)

    // layer 0: input-side gates (K=64), then recurrence
    gemm_tn_f32x2<<<ggrid, 256>>>(x, w_ih0, gi_ptr, MROWS, GATES, IN_DIM);
    gru_rec<<<NBLK, NTHR, rec_smem>>>(w_hh0, b_ih0, b_hh0);

    // layer 1: input-side gates from h1 (K=1024), then recurrence
    gemm_tn_f32x2<<<ggrid, 256>>>(h1_ptr, w_ih1, gi_ptr, MROWS, GATES, HID);
    gru_rec<<<NBLK, NTHR, rec_smem>>>(w_hh1, b_ih1, b_hh1);

    // time-distributed linear on h2 (in g_h1)
    out_linear<<<(MROWS) / 64, 256>>>(w_lin, b_lin, out);
}

// round 6
// speedup vs baseline: 1.5707x; 1.3630x over previous
#include <cuda_runtime.h>
#include <cuda_bf16.h>
#include <math.h>
#include <stdint.h>

#define T_STEPS 512
#define BATCH   128
#define IN_DIM  64
#define HID     1024
#define OUT_DIM 64
#define GATES   (3 * HID)
#define MROWS   (T_STEPS * BATCH)   // 65536
#define NBLK    128
#define RTHR    512

typedef unsigned long long u64;

// Persistent scratch (device globals -- no allocation in kernel_launch).
__device__ float g_gi[(size_t)MROWS * GATES];      // input-side gates
__device__ float g_h1[(size_t)MROWS * HID];        // layer outputs (fp32)
__device__ __nv_bfloat16 g_hhi[2][BATCH * HID];    // hidden state hi plane [m][k]
__device__ __nv_bfloat16 g_hlo[2][BATCH * HID];    // hidden state lo plane
__device__ volatile unsigned g_bar_gen;
__device__ unsigned g_bar_cnt;

// ---------- helpers ----------
__device__ __forceinline__ void fma2(u64 &d, u64 a, u64 b) {
    asm("fma.rn.f32x2 %0, %1, %2, %0;" : "+l"(d) : "l"(a), "l"(b));
}
__device__ __forceinline__ u64 dup2(float x) {
    u64 r; asm("mov.b64 %0, {%1, %1};" : "=l"(r) : "f"(x)); return r;
}
__device__ __forceinline__ float2 unpk(u64 v) {
    float2 r; asm("mov.b64 {%0, %1}, %2;" : "=f"(r.x), "=f"(r.y) : "l"(v)); return r;
}
__device__ __forceinline__ float4 ldcg_f32x4(const void* p) {
    float4 v;
    asm volatile("ld.global.cg.v4.f32 {%0, %1, %2, %3}, [%4];"
                 : "=f"(v.x), "=f"(v.y), "=f"(v.z), "=f"(v.w) : "l"(p));
    return v;
}
__device__ __forceinline__ float ldcg_f32(const void* p) {
    float v;
    asm volatile("ld.global.cg.f32 %0, [%1];" : "=f"(v) : "l"(p));
    return v;
}
__device__ __forceinline__ void cp16(unsigned d, const void* s) {
    asm volatile("cp.async.cg.shared.global [%0], [%1], 16;" :: "r"(d), "l"(s));
}
__device__ __forceinline__ void ldsm4(uint32_t* r, uint32_t a) {
    asm volatile("ldmatrix.sync.aligned.m8n8.x4.shared.b16 {%0,%1,%2,%3}, [%4];"
                 : "=r"(r[0]), "=r"(r[1]), "=r"(r[2]), "=r"(r[3]) : "r"(a));
}
__device__ __forceinline__ void ldsm2t(uint32_t* r, uint32_t a) {
    asm volatile("ldmatrix.sync.aligned.m8n8.x2.trans.shared.b16 {%0,%1}, [%2];"
                 : "=r"(r[0]), "=r"(r[1]) : "r"(a));
}
__device__ __forceinline__ void mma16816(float* c, const uint32_t* a, const uint32_t* b) {
    asm volatile("mma.sync.aligned.m16n8k16.row.col.f32.bf16.bf16.f32 "
                 "{%0,%1,%2,%3}, {%4,%5,%6,%7}, {%8,%9}, {%0,%1,%2,%3};"
                 : "+f"(c[0]), "+f"(c[1]), "+f"(c[2]), "+f"(c[3])
                 : "r"(a[0]), "r"(a[1]), "r"(a[2]), "r"(a[3]), "r"(b[0]), "r"(b[1]));
}
// swizzles (byte-offset XOR, 16B-granular)
__device__ __forceinline__ uint32_t SWA(uint32_t a) { return a ^ ((a >> 3) & 0x10); } // 32B rows
__device__ __forceinline__ uint32_t SWB(uint32_t a) { return a ^ ((a >> 3) & 0x30); } // 64B rows

__device__ __forceinline__ void grid_bar() {
    __threadfence();
    __syncthreads();
    if (threadIdx.x == 0) {
        unsigned gen = g_bar_gen;
        if (atomicAdd(&g_bar_cnt, 1u) == (unsigned)(NBLK - 1)) {
            g_bar_cnt = 0u;
            __threadfence();
            g_bar_gen = gen + 1u;
        } else {
            while (g_bar_gen == gen) { }
        }
        __threadfence();
    }
    __syncthreads();
}

// SMEM layout (bytes)
#define SMEM_BIAS 0                        // 32 floats
#define SMEM_W    1024                     // W hi: [1024 k][32 n] bf16, SWB = 64 KB
#define SMEM_WLO  (1024 + 65536)           // W lo = 64 KB
#define SMEM_ACT  (1024 + 131072)          // 2 bufs x (4 q x 2 pl x [128m][16k]) = 64 KB
#define SMEM_TOT  (SMEM_ACT + 65536)       // 197,632
// red buffer (48 KB fp32 [128 m][24 n][4 q]) aliases SMEM_ACT after k-loop.

// ============================================================================
// GRU recurrence on mma.sync (bf16 3-product split, fp32 accumulate).
// Block owns 8 hidden units (24 gate cols). Warp (p=w&3,q=w>>2):
// m-rows [32p,32p+32) x n24 x k-quarter [256q,256q+256).
// ============================================================================
__global__ void __launch_bounds__(RTHR, 1)
gru_rec_mma(const float* __restrict__ w_hh, const float* __restrict__ b_ih,
            const float* __restrict__ b_hh)
{
    extern __shared__ char smem[];
    const int tid  = threadIdx.x;
    const int wid  = tid >> 5;
    const int lane = tid & 31;
    const int bid  = blockIdx.x;
    const int j0   = bid * 8;
    const int p    = wid & 3;
    const int q    = wid >> 2;
    const uint32_t sb = (uint32_t)__cvta_generic_to_shared(smem);

    // ---- persistent W hi/lo planes: [k][n=gate*8+u], 64B rows, SWB swizzle ----
    for (int idx = tid; idx < 32 * HID; idx += RTHR) {
        int n = idx >> 10, k = idx & 1023;
        float w = 0.0f;
        if (n < 24) w = w_hh[((size_t)(n >> 3) * HID + j0 + (n & 7)) * HID + k];
        __nv_bfloat16 hi = __float2bfloat16(w);
        __nv_bfloat16 lo = __float2bfloat16(w - __bfloat162float(hi));
        uint32_t a = SWB((uint32_t)(k * 64 + n * 2));
        *(__nv_bfloat16*)(smem + SMEM_W   + a) = hi;
        *(__nv_bfloat16*)(smem + SMEM_WLO + a) = lo;
    }
    if (tid < 8) {
        float* sB = (float*)(smem + SMEM_BIAS);
        int j = j0 + tid;
        sB[tid]      = b_ih[j] + b_hh[j];
        sB[8 + tid]  = b_ih[HID + j] + b_hh[HID + j];
        sB[16 + tid] = b_ih[2 * HID + j];
        sB[24 + tid] = b_hh[2 * HID + j];
    }
    // h0 planes = 0
    for (int idx = bid * RTHR + tid; idx < BATCH * HID; idx += NBLK * RTHR) {
        g_hhi[0][idx] = __float2bfloat16(0.0f);
        g_hlo[0][idx] = __float2bfloat16(0.0f);
    }
    __syncthreads();
    grid_bar();

    // ---- per-thread constant maps ----
    // A ldmatrix lane addressing (16x16 quadrants)
    const int relrow = ((lane >> 3) & 1) * 8 + (lane & 7);
    const int segA   = lane >> 4;
    const uint32_t offA0 = SWA((uint32_t)((p * 32 + relrow) * 32 + segA * 16));
    const uint32_t offA1 = SWA((uint32_t)((p * 32 + 16 + relrow) * 32 + segA * 16));
    const int rbB = lane & 15;
    // staging map: 4 x 16B segs per thread per iteration
    const int sqq = tid >> 7;
    const int spl = (tid >> 6) & 1;
    const int smr = (tid * 2) & 127;
    const uint32_t sbase = sb + SMEM_ACT + (uint32_t)(sqq * 8192 + spl * 4096);
    const uint32_t sd0 = sbase + SWA((uint32_t)(smr * 32));
    const uint32_t sd1 = sbase + SWA((uint32_t)(smr * 32 + 16));
    const uint32_t sd2 = sbase + SWA((uint32_t)((smr + 1) * 32));
    const uint32_t sd3 = sbase + SWA((uint32_t)((smr + 1) * 32 + 16));
    // epilogue items
    const int eu = tid & 7;
    const int em = tid >> 3;   // items em and em+64

    for (int t = 0; t < T_STEPS; ++t) {
        const __nv_bfloat16* phi = g_hhi[t & 1];
        const __nv_bfloat16* plo = g_hlo[t & 1];
        __nv_bfloat16* ohi = g_hhi[(t + 1) & 1];
        __nv_bfloat16* olo = g_hlo[(t + 1) & 1];
        const __nv_bfloat16* splane = spl ? plo : phi;
        const __nv_bfloat16* ssrc = splane + (size_t)smr * HID + sqq * 256;

        // stage iteration 0 into buf 0
        cp16(sd0, ssrc);
        cp16(sd1, ssrc + 8);
        cp16(sd2, ssrc + HID);
        cp16(sd3, ssrc + HID + 8);
        asm volatile("cp.async.commit_group;");

        // prefetch epilogue operands
        float gir[2], giz[2], gin[2], hpv[2];
        #pragma unroll
        for (int it = 0; it < 2; ++it) {
            int m = em + it * 64;
            const float* gp = g_gi + ((size_t)t * BATCH + m) * GATES + j0 + eu;
            gir[it] = ldcg_f32(gp);
            giz[it] = ldcg_f32(gp + HID);
            gin[it] = ldcg_f32(gp + 2 * HID);
            hpv[it] = t ? ldcg_f32(g_h1 + ((size_t)(t - 1) * BATCH + m) * HID + j0 + eu)
                        : 0.0f;
        }

        float c[2][3][4];
        #pragma unroll
        for (int mt = 0; mt < 2; ++mt)
            #pragma unroll
            for (int g = 0; g < 3; ++g)
                #pragma unroll
                for (int r = 0; r < 4; ++r) c[mt][g][r] = 0.0f;

        #pragma unroll 1
        for (int i = 0; i < 16; ++i) {
            if (i + 1 < 16) {
                const __nv_bfloat16* s = ssrc + (i + 1) * 16;
                uint32_t bofs = (uint32_t)(((i + 1) & 1) * 32768);
                cp16(sd0 + bofs, s);
                cp16(sd1 + bofs, s + 8);
                cp16(sd2 + bofs, s + HID);
                cp16(sd3 + bofs, s + HID + 8);
                asm volatile("cp.async.commit_group;");
                asm volatile("cp.async.wait_group 1;");
            } else {
                asm volatile("cp.async.wait_group 0;");
            }
            __syncthreads();

            // B fragments for this k16 (3 gates x hi/lo)
            const int kb = q * 256 + i * 16;
            const uint32_t bbase = (uint32_t)((kb + rbB) * 64);
            uint32_t bh[3][2], bl[3][2];
            #pragma unroll
            for (int g = 0; g < 3; ++g) {
                uint32_t a = SWB(bbase + (uint32_t)(g * 16));
                ldsm2t(bh[g], sb + SMEM_W + a);
                ldsm2t(bl[g], sb + SMEM_WLO + a);
            }
            const uint32_t actq = sb + SMEM_ACT + (uint32_t)((i & 1) * 32768 + q * 8192);
            #pragma unroll
            for (int mt = 0; mt < 2; ++mt) {
                uint32_t off = mt ? offA1 : offA0;
                uint32_t ah[4], al[4];
                ldsm4(ah, actq + off);
                ldsm4(al, actq + 4096 + off);
                #pragma unroll
                for (int g = 0; g < 3; ++g) {
                    mma16816(c[mt][g], ah, bh[g]);
                    mma16816(c[mt][g], al, bh[g]);
                    mma16816(c[mt][g], ah, bl[g]);
                }
            }
            __syncthreads();
        }

        // ---- k-split reduction through smem (aliases act buffers) ----
        float* red = (float*)(smem + SMEM_ACT);   // [128 m][24 n][4 q]
        {
            const int r0 = p * 32 + (lane >> 2);
            const int c2 = (lane & 3) * 2;
            #pragma unroll
            for (int mt = 0; mt < 2; ++mt) {
                int rr = r0 + mt * 16;
                #pragma unroll
                for (int g = 0; g < 3; ++g) {
                    int nn = g * 8 + c2;
                    red[(rr * 24 + nn) * 4 + q]           = c[mt][g][0];
                    red[(rr * 24 + nn + 1) * 4 + q]       = c[mt][g][1];
                    red[((rr + 8) * 24 + nn) * 4 + q]     = c[mt][g][2];
                    red[((rr + 8) * 24 + nn + 1) * 4 + q] = c[mt][g][3];
                }
            }
        }
        __syncthreads();

        // ---- epilogue: gate math, h writeback ----
        {
            const float* sB = (const float*)(smem + SMEM_BIAS);
            #pragma unroll
            for (int it = 0; it < 2; ++it) {
                int m = em + it * 64;
                float4 vr = *(const float4*)(red + ((size_t)m * 24 + eu) * 4);
                float4 vz = *(const float4*)(red + ((size_t)m * 24 + 8 + eu) * 4);
                float4 vn = *(const float4*)(red + ((size_t)m * 24 + 16 + eu) * 4);
                float ghr = (vr.x + vr.y) + (vr.z + vr.w);
                float ghz = (vz.x + vz.y) + (vz.z + vz.w);
                float ghn = (vn.x + vn.y) + (vn.z + vn.w);
                float rg = 1.0f / (1.0f + expf(-(gir[it] + ghr + sB[eu])));
                float zg = 1.0f / (1.0f + expf(-(giz[it] + ghz + sB[8 + eu])));
                float ng = tanhf(gin[it] + sB[16 + eu] + rg * (ghn + sB[24 + eu]));
                float h  = (1.0f - zg) * ng + zg * hpv[it];

                __nv_bfloat16 hi = __float2bfloat16(h);
                __nv_bfloat16 lo = __float2bfloat16(h - __bfloat162float(hi));
                ohi[(size_t)m * HID + j0 + eu] = hi;
                olo[(size_t)m * HID + j0 + eu] = lo;
                g_h1[((size_t)t * BATCH + m) * HID + j0 + eu] = h;
            }
        }

        grid_bar();
    }
}

// ============================================================================
// C[m][n] = sum_k A[m][k] * B[n][k]  (both k-contiguous), f32x2 inner.
// ============================================================================
#define GKC 16
__global__ void __launch_bounds__(256)
gemm_tn_f32x2(const float* __restrict__ A, const float* __restrict__ B,
              float* __restrict__ C, int M, int N, int K)
{
    __shared__ float sA[GKC][132];
    __shared__ float sB[GKC][132];
    const int tid = threadIdx.x;
    const int m0  = blockIdx.y * 128;
    const int n0  = blockIdx.x * 128;
    const int ty  = tid >> 4, tx = tid & 15;

    const int sr = tid >> 1;
    const int sk = (tid & 1) * 8;

    u64 acc[4][8];
    #pragma unroll
    for (int p = 0; p < 4; ++p)
        #pragma unroll
        for (int c = 0; c < 8; ++c) acc[p][c] = 0ull;

    const float* Ag = A + (size_t)(m0 + sr) * K + sk;
    const float* Bg = B + (size_t)(n0 + sr) * K + sk;

    float4 a0 = ldcg_f32x4(Ag);
    float4 a1 = ldcg_f32x4(Ag + 4);
    float4 b0 = ldcg_f32x4(Bg);
    float4 b1 = ldcg_f32x4(Bg + 4);

    for (int kc = 0; kc < K; kc += GKC) {
        sA[sk + 0][sr] = a0.x; sA[sk + 1][sr] = a0.y;
        sA[sk + 2][sr] = a0.z; sA[sk + 3][sr] = a0.w;
        sA[sk + 4][sr] = a1.x; sA[sk + 5][sr] = a1.y;
        sA[sk + 6][sr] = a1.z; sA[sk + 7][sr] = a1.w;
        sB[sk + 0][sr] = b0.x; sB[sk + 1][sr] = b0.y;
        sB[sk + 2][sr] = b0.z; sB[sk + 3][sr] = b0.w;
        sB[sk + 4][sr] = b1.x; sB[sk + 5][sr] = b1.y;
        sB[sk + 6][sr] = b1.z; sB[sk + 7][sr] = b1.w;
        if (kc + GKC < K) {
            Ag += GKC; Bg += GKC;
            a0 = ldcg_f32x4(Ag);
            a1 = ldcg_f32x4(Ag + 4);
            b0 = ldcg_f32x4(Bg);
            b1 = ldcg_f32x4(Bg + 4);
        }
        __syncthreads();

        #pragma unroll
        for (int kk = 0; kk < GKC; ++kk) {
            ulonglong2 aa = *(const ulonglong2*)(&sA[kk][ty * 8]);
            ulonglong2 ab = *(const ulonglong2*)(&sA[kk][ty * 8 + 4]);
            float4 bv0 = *(const float4*)(&sB[kk][tx * 8]);
            float4 bv1 = *(const float4*)(&sB[kk][tx * 8 + 4]);
            float bs[8] = {bv0.x, bv0.y, bv0.z, bv0.w, bv1.x, bv1.y, bv1.z, bv1.w};
            #pragma unroll
            for (int c = 0; c < 8; ++c) {
                u64 bd = dup2(bs[c]);
                fma2(acc[0][c], aa.x, bd);
                fma2(acc[1][c], aa.y, bd);
                fma2(acc[2][c], ab.x, bd);
                fma2(acc[3][c], ab.y, bd);
            }
        }
        __syncthreads();
    }

    #pragma unroll
    for (int p = 0; p < 4; ++p) {
        float2 v[8];
        #pragma unroll
        for (int c = 0; c < 8; ++c) v[c] = unpk(acc[p][c]);
        int row0 = m0 + ty * 8 + p * 2;
        float* c0 = C + (size_t)row0 * N + n0 + tx * 8;
        float* c1 = c0 + N;
        *(float4*)(c0)     = make_float4(v[0].x, v[1].x, v[2].x, v[3].x);
        *(float4*)(c0 + 4) = make_float4(v[4].x, v[5].x, v[6].x, v[7].x);
        *(float4*)(c1)     = make_float4(v[0].y, v[1].y, v[2].y, v[3].y);
        *(float4*)(c1 + 4) = make_float4(v[4].y, v[5].y, v[6].y, v[7].y);
    }
}

// ============================================================================
// out[t,b,o] = h2[t,b,:] . w_lin[o,:] + b_lin[o]  (h2 lives in g_h1)
// ============================================================================
__global__ void __launch_bounds__(256)
out_linear(const float* __restrict__ w_lin, const float* __restrict__ b_lin,
           float* __restrict__ out)
{
    __shared__ float sA[16][68];
    __shared__ float sB[16][68];
    const int tid = threadIdx.x;
    const size_t rb = (size_t)blockIdx.x * 64;
    const int ty = tid >> 4;
    const int tx = tid & 15;

    const int li   = tid * 4;
    const int srow = li >> 4;
    const int skk  = li & 15;

    float acc[4][4] = {};

    for (int kc = 0; kc < HID; kc += 16) {
        __syncthreads();
        float4 va = ldcg_f32x4(g_h1 + (rb + srow) * HID + kc + skk);
        sA[skk + 0][srow] = va.x; sA[skk + 1][srow] = va.y;
        sA[skk + 2][srow] = va.z; sA[skk + 3][srow] = va.w;
        float4 vb = *(const float4*)(w_lin + (size_t)srow * HID + kc + skk);
        sB[skk + 0][srow] = vb.x; sB[skk + 1][srow] = vb.y;
        sB[skk + 2][srow] = vb.z; sB[skk + 3][srow] = vb.w;
        __syncthreads();
        #pragma unroll
        for (int kk = 0; kk < 16; ++kk) {
            float4 a = *(const float4*)&sA[kk][ty * 4];
            float4 b = *(const float4*)&sB[kk][tx * 4];
            acc[0][0] = fmaf(a.x, b.x, acc[0][0]); acc[0][1] = fmaf(a.x, b.y, acc[0][1]);
            acc[0][2] = fmaf(a.x, b.z, acc[0][2]); acc[0][3] = fmaf(a.x, b.w, acc[0][3]);
            acc[1][0] = fmaf(a.y, b.x, acc[1][0]); acc[1][1] = fmaf(a.y, b.y, acc[1][1]);
            acc[1][2] = fmaf(a.y, b.z, acc[1][2]); acc[1][3] = fmaf(a.y, b.w, acc[1][3]);
            acc[2][0] = fmaf(a.z, b.x, acc[2][0]); acc[2][1] = fmaf(a.z, b.y, acc[2][1]);
            acc[2][2] = fmaf(a.z, b.z, acc[2][2]); acc[2][3] = fmaf(a.z, b.w, acc[2][3]);
            acc[3][0] = fmaf(a.w, b.x, acc[3][0]); acc[3][1] = fmaf(a.w, b.y, acc[3][1]);
            acc[3][2] = fmaf(a.w, b.z, acc[3][2]); acc[3][3] = fmaf(a.w, b.w, acc[3][3]);
        }
    }

    #pragma unroll
    for (int i = 0; i < 4; ++i) {
        float4 o4;
        o4.x = acc[i][0] + b_lin[tx * 4 + 0];
        o4.y = acc[i][1] + b_lin[tx * 4 + 1];
        o4.z = acc[i][2] + b_lin[tx * 4 + 2];
        o4.w = acc[i][3] + b_lin[tx * 4 + 3];
        *(float4*)(out + (rb + ty * 4 + i) * OUT_DIM + tx * 4) = o4;
    }
}

extern "C" void kernel_launch(void* const* d_in, const int* in_sizes, int n_in,
                              void* d_out, int out_size)
{
    const float* x     = (const float*)d_in[0];
    const float* w_ih0 = (const float*)d_in[1];
    const float* w_hh0 = (const float*)d_in[2];
    const float* b_ih0 = (const float*)d_in[3];
    const float* b_hh0 = (const float*)d_in[4];
    const float* w_ih1 = (const float*)d_in[5];
    const float* w_hh1 = (const float*)d_in[6];
    const float* b_ih1 = (const float*)d_in[7];
    const float* b_hh1 = (const float*)d_in[8];
    const float* w_lin = (const float*)d_in[9];
    const float* b_lin = (const float*)d_in[10];
    float* out = (float*)d_out;
    (void)in_sizes; (void)n_in; (void)out_size;

    float *gi_ptr, *h1_ptr;
    cudaGetSymbolAddress((void**)&gi_ptr, g_gi);
    cudaGetSymbolAddress((void**)&h1_ptr, g_h1);

    cudaFuncSetAttribute(gru_rec_mma, cudaFuncAttributeMaxDynamicSharedMemorySize, SMEM_TOT);

    dim3 ggrid(GATES / 128, MROWS / 128);   // (24, 512)

    // layer 0: input-side gates (K=64), then recurrence
    gemm_tn_f32x2<<<ggrid, 256>>>(x, w_ih0, gi_ptr, MROWS, GATES, IN_DIM);
    gru_rec_mma<<<NBLK, RTHR, SMEM_TOT>>>(w_hh0, b_ih0, b_hh0);

    // layer 1: input-side gates from h1 (K=1024), then recurrence
    gemm_tn_f32x2<<<ggrid, 256>>>(h1_ptr, w_ih1, gi_ptr, MROWS, GATES, HID);
    gru_rec_mma<<<NBLK, RTHR, SMEM_TOT>>>(w_hh1, b_ih1, b_hh1);

    // time-distributed linear on h2 (in g_h1)
    out_linear<<<MROWS / 64, 256>>>(w_lin, b_lin, out);
}

// round 8
// speedup vs baseline: 2.1433x; 1.3646x over previous
#include <cuda_runtime.h>
#include <cuda_bf16.h>
#include <math.h>
#include <stdint.h>

#define T_STEPS 512
#define BATCH   128
#define IN_DIM  64
#define HID     1024
#define OUT_DIM 64
#define GATES   (3 * HID)
#define MROWS   (T_STEPS * BATCH)   // 65536
#define NBLK    128
#define RTHR    512

typedef unsigned long long u64;

// Persistent scratch (device globals -- no allocation anywhere).
__device__ float g_gi[(size_t)MROWS * GATES];        // input-side gates
__device__ float g_h1[(size_t)MROWS * HID];          // layer outputs (fp32)
__device__ __nv_bfloat16 g_h1hi[(size_t)MROWS * HID];// layer outputs, bf16 hi plane
__device__ __nv_bfloat16 g_h1lo[(size_t)MROWS * HID];// layer outputs, bf16 lo plane
__device__ __nv_bfloat16 g_hzero[BATCH * HID];       // zeros (h_{-1})
__device__ __nv_bfloat16 g_wbhi[(size_t)HID * GATES];// w_ih1 transposed [k][n], hi
__device__ __nv_bfloat16 g_wblo[(size_t)HID * GATES];// lo
__device__ volatile unsigned g_bar_gen;
__device__ unsigned g_bar_cnt;

// ---------- helpers ----------
__device__ __forceinline__ void fma2(u64 &d, u64 a, u64 b) {
    asm("fma.rn.f32x2 %0, %1, %2, %0;" : "+l"(d) : "l"(a), "l"(b));
}
__device__ __forceinline__ u64 dup2(float x) {
    u64 r; asm("mov.b64 %0, {%1, %1};" : "=l"(r) : "f"(x)); return r;
}
__device__ __forceinline__ float2 unpk(u64 v) {
    float2 r; asm("mov.b64 {%0, %1}, %2;" : "=f"(r.x), "=f"(r.y) : "l"(v)); return r;
}
__device__ __forceinline__ float4 ldcg_f32x4(const void* p) {
    float4 v;
    asm volatile("ld.global.cg.v4.f32 {%0, %1, %2, %3}, [%4];"
                 : "=f"(v.x), "=f"(v.y), "=f"(v.z), "=f"(v.w) : "l"(p));
    return v;
}
__device__ __forceinline__ float ldcg_f32(const void* p) {
    float v;
    asm volatile("ld.global.cg.f32 %0, [%1];" : "=f"(v) : "l"(p));
    return v;
}
__device__ __forceinline__ void cp16(unsigned d, const void* s) {
    asm volatile("cp.async.cg.shared.global [%0], [%1], 16;" :: "r"(d), "l"(s));
}
__device__ __forceinline__ void ldsm4(uint32_t* r, uint32_t a) {
    asm volatile("ldmatrix.sync.aligned.m8n8.x4.shared.b16 {%0,%1,%2,%3}, [%4];"
                 : "=r"(r[0]), "=r"(r[1]), "=r"(r[2]), "=r"(r[3]) : "r"(a));
}
__device__ __forceinline__ void ldsm2t(uint32_t* r, uint32_t a) {
    asm volatile("ldmatrix.sync.aligned.m8n8.x2.trans.shared.b16 {%0,%1}, [%2];"
                 : "=r"(r[0]), "=r"(r[1]) : "r"(a));
}
__device__ __forceinline__ void mma16816(float* c, const uint32_t* a, const uint32_t* b) {
    asm volatile("mma.sync.aligned.m16n8k16.row.col.f32.bf16.bf16.f32 "
                 "{%0,%1,%2,%3}, {%4,%5,%6,%7}, {%8,%9}, {%0,%1,%2,%3};"
                 : "+f"(c[0]), "+f"(c[1]), "+f"(c[2]), "+f"(c[3])
                 : "r"(a[0]), "r"(a[1]), "r"(a[2]), "r"(a[3]), "r"(b[0]), "r"(b[1]));
}
// swizzles (byte-offset XOR)
__device__ __forceinline__ uint32_t SWA(uint32_t a) { return a ^ ((a >> 3) & 0x10); }  // 32B rows
__device__ __forceinline__ uint32_t SWB(uint32_t a) { return a ^ ((a >> 3) & 0x30); }  // 64B rows
// 256B-row B tile: XOR the 16B-chunk column by (row&7)
__device__ __forceinline__ uint32_t SWR(int row, uint32_t c) { return c ^ (((uint32_t)row & 7u) << 4); }

__device__ __forceinline__ void grid_bar() {
    __threadfence();
    __syncthreads();
    if (threadIdx.x == 0) {
        unsigned gen = g_bar_gen;
        if (atomicAdd(&g_bar_cnt, 1u) == (unsigned)(NBLK - 1)) {
            g_bar_cnt = 0u;
            __threadfence();
            g_bar_gen = gen + 1u;
        } else {
            while (g_bar_gen == gen) { }
        }
        __threadfence();
    }
    __syncthreads();
}

// rec smem layout
#define SMEM_BIAS 0
#define SMEM_W    1024                   // W hi: [1024k][32n] bf16 SWB = 64 KB
#define SMEM_WLO  (1024 + 65536)
#define SMEM_ACT  (1024 + 131072)        // 16 warps x 3 bufs x 2 KB rings (red aliases)
#define SMEM_TOT  (SMEM_ACT + 98304)     // 230,400 B

// ============================================================================
// GRU recurrence on mma.sync; warp-private cp.async rings (no block syncs in
// k-loop). Warp (p=w&3, q=w>>2): m-rows [32p,32p+32) x n24 x k [256q,256q+256).
// ============================================================================
__global__ void __launch_bounds__(RTHR, 1)
gru_rec_mma(const float* __restrict__ w_hh, const float* __restrict__ b_ih,
            const float* __restrict__ b_hh)
{
    extern __shared__ char smem[];
    const int tid  = threadIdx.x;
    const int wid  = tid >> 5;
    const int lane = tid & 31;
    const int bid  = blockIdx.x;
    const int j0   = bid * 8;
    const int p    = wid & 3;
    const int q    = wid >> 2;
    const uint32_t sb = (uint32_t)__cvta_generic_to_shared(smem);

    // persistent W hi/lo: [k][n=gate*8+u] 64B rows, SWB
    for (int idx = tid; idx < 32 * HID; idx += RTHR) {
        int n = idx >> 10, k = idx & 1023;
        float w = 0.0f;
        if (n < 24) w = w_hh[((size_t)(n >> 3) * HID + j0 + (n & 7)) * HID + k];
        __nv_bfloat16 hi = __float2bfloat16(w);
        __nv_bfloat16 lo = __float2bfloat16(w - __bfloat162float(hi));
        uint32_t a = SWB((uint32_t)(k * 64 + n * 2));
        *(__nv_bfloat16*)(smem + SMEM_W   + a) = hi;
        *(__nv_bfloat16*)(smem + SMEM_WLO + a) = lo;
    }
    if (tid < 8) {
        float* sB = (float*)(smem + SMEM_BIAS);
        int j = j0 + tid;
        sB[tid]      = b_ih[j] + b_hh[j];
        sB[8 + tid]  = b_ih[HID + j] + b_hh[HID + j];
        sB[16 + tid] = b_ih[2 * HID + j];
        sB[24 + tid] = b_hh[2 * HID + j];
    }
    for (int idx = bid * RTHR + tid; idx < BATCH * HID; idx += NBLK * RTHR)
        g_hzero[idx] = __float2bfloat16(0.0f);
    __syncthreads();
    grid_bar();

    // lane-constant maps
    const int relrow = ((lane >> 3) & 1) * 8 + (lane & 7);
    const int segA   = lane >> 4;
    const uint32_t offA0 = SWA((uint32_t)(relrow * 32 + segA * 16));
    const uint32_t offA1 = SWA((uint32_t)((16 + relrow) * 32 + segA * 16));
    const int rbB = lane & 15;
    // warp-private staging: lane -> plane spl, rows r0, r0+1
    const int spl = lane >> 4;
    const int r0  = (lane & 15) * 2;
    const uint32_t ring0 = sb + SMEM_ACT + (uint32_t)(wid * 6144);
    const uint32_t d00 = (uint32_t)(spl * 1024) + SWA((uint32_t)(r0 * 32));
    const uint32_t d01 = (uint32_t)(spl * 1024) + SWA((uint32_t)(r0 * 32 + 16));
    const uint32_t d10 = (uint32_t)(spl * 1024) + SWA((uint32_t)((r0 + 1) * 32));
    const uint32_t d11 = (uint32_t)(spl * 1024) + SWA((uint32_t)((r0 + 1) * 32 + 16));
    const int eu = tid & 7;
    const int em = tid >> 3;

    for (int t = 0; t < T_STEPS; ++t) {
        const __nv_bfloat16* hi_src = t ? g_h1hi + (size_t)(t - 1) * BATCH * HID : g_hzero;
        const __nv_bfloat16* lo_src = t ? g_h1lo + (size_t)(t - 1) * BATCH * HID : g_hzero;
        const __nv_bfloat16* sp = (spl ? lo_src : hi_src)
                                + (size_t)(32 * p + r0) * HID + q * 256;

        // prologue: stage chunks 0,1 into ring bufs 0,1
        #pragma unroll
        for (int pre = 0; pre < 2; ++pre) {
            uint32_t base = ring0 + (uint32_t)(pre * 2048);
            const __nv_bfloat16* s = sp + pre * 16;
            cp16(base + d00, s);       cp16(base + d01, s + 8);
            cp16(base + d10, s + HID); cp16(base + d11, s + HID + 8);
            asm volatile("cp.async.commit_group;");
        }

        // epilogue operand prefetch
        float gir[2], giz[2], gin[2], hpv[2];
        #pragma unroll
        for (int it = 0; it < 2; ++it) {
            int m = em + it * 64;
            const float* gp = g_gi + ((size_t)t * BATCH + m) * GATES + j0 + eu;
            gir[it] = ldcg_f32(gp);
            giz[it] = ldcg_f32(gp + HID);
            gin[it] = ldcg_f32(gp + 2 * HID);
            hpv[it] = t ? ldcg_f32(g_h1 + ((size_t)(t - 1) * BATCH + m) * HID + j0 + eu)
                        : 0.0f;
        }

        float c[2][3][4];
        #pragma unroll
        for (int mt = 0; mt < 2; ++mt)
            #pragma unroll
            for (int g = 0; g < 3; ++g)
                #pragma unroll
                for (int r = 0; r < 4; ++r) c[mt][g][r] = 0.0f;

        #pragma unroll 1
        for (int i = 0; i < 16; ++i) {
            if (i + 2 < 16) {
                uint32_t base = ring0 + (uint32_t)(((i + 2) % 3) * 2048);
                const __nv_bfloat16* s = sp + (i + 2) * 16;
                cp16(base + d00, s);       cp16(base + d01, s + 8);
                cp16(base + d10, s + HID); cp16(base + d11, s + HID + 8);
                asm volatile("cp.async.commit_group;");
                asm volatile("cp.async.wait_group 2;");
            } else if (i == 14) {
                asm volatile("cp.async.wait_group 1;");
            } else {
                asm volatile("cp.async.wait_group 0;");
            }
            __syncwarp();

            const int kb = q * 256 + i * 16;
            const uint32_t bbase = (uint32_t)((kb + rbB) * 64);
            uint32_t bh[3][2], bl[3][2];
            #pragma unroll
            for (int g = 0; g < 3; ++g) {
                uint32_t a = SWB(bbase + (uint32_t)(g * 16));
                ldsm2t(bh[g], sb + SMEM_W + a);
                ldsm2t(bl[g], sb + SMEM_WLO + a);
            }
            const uint32_t abase = ring0 + (uint32_t)((i % 3) * 2048);
            #pragma unroll
            for (int mt = 0; mt < 2; ++mt) {
                uint32_t off = mt ? offA1 : offA0;
                uint32_t ah[4], al[4];
                ldsm4(ah, abase + off);
                ldsm4(al, abase + 1024 + off);
                #pragma unroll
                for (int g = 0; g < 3; ++g) {
                    mma16816(c[mt][g], ah, bh[g]);
                    mma16816(c[mt][g], al, bh[g]);
                    mma16816(c[mt][g], ah, bl[g]);
                }
            }
        }

        __syncthreads();   // rings idle; red aliases them
        float* red = (float*)(smem + SMEM_ACT);   // [128 m][24 n][4 q]
        {
            const int rr0 = p * 32 + (lane >> 2);
            const int c2  = (lane & 3) * 2;
            #pragma unroll
            for (int mt = 0; mt < 2; ++mt) {
                int rr = rr0 + mt * 16;
                #pragma unroll
                for (int g = 0; g < 3; ++g) {
                    int nn = g * 8 + c2;
                    red[(rr * 24 + nn) * 4 + q]           = c[mt][g][0];
                    red[(rr * 24 + nn + 1) * 4 + q]       = c[mt][g][1];
                    red[((rr + 8) * 24 + nn) * 4 + q]     = c[mt][g][2];
                    red[((rr + 8) * 24 + nn + 1) * 4 + q] = c[mt][g][3];
                }
            }
        }
        __syncthreads();

        {
            const float* sB = (const float*)(smem + SMEM_BIAS);
            #pragma unroll
            for (int it = 0; it < 2; ++it) {
                int m = em + it * 64;
                float4 vr = *(const float4*)(red + ((size_t)m * 24 + eu) * 4);
                float4 vz = *(const float4*)(red + ((size_t)m * 24 + 8 + eu) * 4);
                float4 vn = *(const float4*)(red + ((size_t)m * 24 + 16 + eu) * 4);
                float ghr = (vr.x + vr.y) + (vr.z + vr.w);
                float ghz = (vz.x + vz.y) + (vz.z + vz.w);
                float ghn = (vn.x + vn.y) + (vn.z + vn.w);
                float rg = 1.0f / (1.0f + expf(-(gir[it] + ghr + sB[eu])));
                float zg = 1.0f / (1.0f + expf(-(giz[it] + ghz + sB[8 + eu])));
                float ng = tanhf(gin[it] + sB[16 + eu] + rg * (ghn + sB[24 + eu]));
                float h  = (1.0f - zg) * ng + zg * hpv[it];

                __nv_bfloat16 hi = __float2bfloat16(h);
                __nv_bfloat16 lo = __float2bfloat16(h - __bfloat162float(hi));
                size_t o = ((size_t)t * BATCH + m) * HID + j0 + eu;
                g_h1hi[o] = hi;
                g_h1lo[o] = lo;
                g_h1[o]   = h;
            }
        }

        grid_bar();
    }
}

// ============================================================================
// Transpose + bf16-split w_ih1: [3072 n][1024 k] fp32 -> [k][n] hi/lo planes.
// ============================================================================
__global__ void __launch_bounds__(256)
conv_w(const float* __restrict__ w)
{
    __shared__ float tile[32][33];
    const int tx = threadIdx.x & 31;
    const int ty = threadIdx.x >> 5;       // 0..7
    const int k0 = blockIdx.x * 32;
    const int n0 = blockIdx.y * 32;
    #pragma unroll
    for (int r = 0; r < 4; ++r)
        tile[ty + r * 8][tx] = w[(size_t)(n0 + ty + r * 8) * HID + k0 + tx];
    __syncthreads();
    #pragma unroll
    for (int r = 0; r < 4; ++r) {
        float v = tile[tx][ty + r * 8];
        __nv_bfloat16 hi = __float2bfloat16(v);
        __nv_bfloat16 lo = __float2bfloat16(v - __bfloat162float(hi));
        size_t o = (size_t)(k0 + ty + r * 8) * GATES + n0 + tx;
        g_wbhi[o] = hi;
        g_wblo[o] = lo;
    }
}

// ============================================================================
// gi1 = h1 @ w_ih1^T on mma.sync (bf16 3-split). Tile 128m x 128n, K=1024.
// Stage = A[2pl][128m][32B] (8KB, SWA) + B[2pl][16k][256B] (8KB, SWR) = 16KB.
// 4-deep ring in dynamic smem (64 KB). 512 thr: tid<256 stage A, >=256 stage B.
// ============================================================================
#define GST 16384
__global__ void __launch_bounds__(512)
gemm_bf16_3s(float* __restrict__ C)
{
    extern __shared__ char gsm[];   // 4 * 16384
    const int tid  = threadIdx.x;
    const int wid  = tid >> 5;
    const int lane = tid & 31;
    const int m0 = blockIdx.y * 128;
    const int n0 = blockIdx.x * 128;
    const int p  = wid & 3;
    const int nq = wid >> 2;
    const uint32_t sb = (uint32_t)__cvta_generic_to_shared(gsm);

    const int relrow = ((lane >> 3) & 1) * 8 + (lane & 7);
    const int segA   = lane >> 4;
    const uint32_t offA0 = SWA((uint32_t)((p * 32 + relrow) * 32 + segA * 16));
    const uint32_t offA1 = SWA((uint32_t)((p * 32 + 16 + relrow) * 32 + segA * 16));
    const int rbB = lane & 15;
    // B fragment smem offsets (per plane): row rbB, col (nq*64 + nt*16) ^ ((row&7)<<4)
    uint32_t offB[4];
    #pragma unroll
    for (int nt = 0; nt < 4; ++nt)
        offB[nt] = (uint32_t)(8192 + rbB * 256) + SWR(rbB, (uint32_t)(nq * 64 + nt * 16));

    // staging maps
    const bool stA = (tid < 256);
    const int  apl = (tid >> 7) & 1;        // A plane
    const int  am  = tid & 127;             // A m-row
    const int  bix = tid & 255;             // for tid>=256: 0..255
    const int  bpl = bix >> 7;              // B plane
    const int  brw = (bix & 127) >> 3;      // B k-row 0..15
    const int  bcs = (bix & 7) * 32;        // B col byte 0..224

    const __nv_bfloat16* Asrc = (apl ? g_h1lo : g_h1hi) + (size_t)(m0 + am) * HID;
    const __nv_bfloat16* Bpl  = (bpl ? g_wblo : g_wbhi) + n0 + bcs / 2;
    const uint32_t adst0 = (uint32_t)(apl * 4096) + SWA((uint32_t)(am * 32));
    const uint32_t adst1 = (uint32_t)(apl * 4096) + SWA((uint32_t)(am * 32 + 16));
    const uint32_t bdst0 = (uint32_t)(8192 + bpl * 4096 + brw * 256)
                         + SWR(brw, (uint32_t)bcs);
    const uint32_t bdst1 = (uint32_t)(8192 + bpl * 4096 + brw * 256)
                         + SWR(brw, (uint32_t)(bcs + 16));

    float c[2][4][4];
    #pragma unroll
    for (int mt = 0; mt < 2; ++mt)
        #pragma unroll
        for (int nt = 0; nt < 4; ++nt)
            #pragma unroll
            for (int r = 0; r < 4; ++r) c[mt][nt][r] = 0.0f;

    // prologue: stage chunks 0,1,2
    #pragma unroll
    for (int pre = 0; pre < 3; ++pre) {
        uint32_t base = sb + (uint32_t)(pre * GST);
        if (stA) {
            cp16(base + adst0, Asrc + pre * 16);
            cp16(base + adst1, Asrc + pre * 16 + 8);
        } else {
            const __nv_bfloat16* s = Bpl + (size_t)(pre * 16 + brw) * GATES;
            cp16(base + bdst0, s);
            cp16(base + bdst1, s + 8);
        }
        asm volatile("cp.async.commit_group;");
    }

    #pragma unroll 1
    for (int i = 0; i < 64; ++i) {
        __syncthreads();   // all warps done reading the buffer about to be overwritten
        if (i + 3 < 64) {
            uint32_t base = sb + (uint32_t)(((i + 3) & 3) * GST);
            if (stA) {
                cp16(base + adst0, Asrc + (i + 3) * 16);
                cp16(base + adst1, Asrc + (i + 3) * 16 + 8);
            } else {
                const __nv_bfloat16* s = Bpl + (size_t)((i + 3) * 16 + brw) * GATES;
                cp16(base + bdst0, s);
                cp16(base + bdst1, s + 8);
            }
            asm volatile("cp.async.commit_group;");
            asm volatile("cp.async.wait_group 3;");
        } else {
            asm volatile("cp.async.wait_group 0;");
        }
        __syncthreads();   // chunk i visible to all

        const uint32_t base = sb + (uint32_t)((i & 3) * GST);
        uint32_t bh[4][2], bl[4][2];
        #pragma unroll
        for (int nt = 0; nt < 4; ++nt) {
            ldsm2t(bh[nt], base + offB[nt]);
            ldsm2t(bl[nt], base + offB[nt] + 4096);
        }
        #pragma unroll
        for (int mt = 0; mt < 2; ++mt) {
            uint32_t off = mt ? offA1 : offA0;
            uint32_t ah[4], al[4];
            ldsm4(ah, base + off);
            ldsm4(al, base + 4096 + off);
            #pragma unroll
            for (int nt = 0; nt < 4; ++nt) {
                mma16816(c[mt][nt], ah, bh[nt]);
                mma16816(c[mt][nt], al, bh[nt]);
                mma16816(c[mt][nt], ah, bl[nt]);
            }
        }
    }

    // writeback
    #pragma unroll
    for (int mt = 0; mt < 2; ++mt) {
        int row = m0 + p * 32 + mt * 16 + (lane >> 2);
        #pragma unroll
        for (int nt = 0; nt < 4; ++nt) {
            int col = n0 + nq * 32 + nt * 8 + (lane & 3) * 2;
            *(float2*)(C + (size_t)row * GATES + col) =
                make_float2(c[mt][nt][0], c[mt][nt][1]);
            *(float2*)(C + (size_t)(row + 8) * GATES + col) =
                make_float2(c[mt][nt][2], c[mt][nt][3]);
        }
    }
}

// ============================================================================
// gi0 = x @ w_ih0^T  (K=64, fp32 f32x2)
// ============================================================================
#define GKC 16
__global__ void __launch_bounds__(256)
gemm_tn_f32x2(const float* __restrict__ A, const float* __restrict__ B,
              float* __restrict__ C, int M, int N, int K)
{
    __shared__ float sA[GKC][132];
    __shared__ float sB[GKC][132];
    const int tid = threadIdx.x;
    const int m0  = blockIdx.y * 128;
    const int n0  = blockIdx.x * 128;
    const int ty  = tid >> 4, tx = tid & 15;
    const int sr = tid >> 1;
    const int sk = (tid & 1) * 8;

    u64 acc[4][8];
    #pragma unroll
    for (int p = 0; p < 4; ++p)
        #pragma unroll
        for (int c = 0; c < 8; ++c) acc[p][c] = 0ull;

    const float* Ag = A + (size_t)(m0 + sr) * K + sk;
    const float* Bg = B + (size_t)(n0 + sr) * K + sk;
    float4 a0 = ldcg_f32x4(Ag);
    float4 a1 = ldcg_f32x4(Ag + 4);
    float4 b0 = ldcg_f32x4(Bg);
    float4 b1 = ldcg_f32x4(Bg + 4);

    for (int kc = 0; kc < K; kc += GKC) {
        sA[sk + 0][sr] = a0.x; sA[sk + 1][sr] = a0.y;
        sA[sk + 2][sr] = a0.z; sA[sk + 3][sr] = a0.w;
        sA[sk + 4][sr] = a1.x; sA[sk + 5][sr] = a1.y;
        sA[sk + 6][sr] = a1.z; sA[sk + 7][sr] = a1.w;
        sB[sk + 0][sr] = b0.x; sB[sk + 1][sr] = b0.y;
        sB[sk + 2][sr] = b0.z; sB[sk + 3][sr] = b0.w;
        sB[sk + 4][sr] = b1.x; sB[sk + 5][sr] = b1.y;
        sB[sk + 6][sr] = b1.z; sB[sk + 7][sr] = b1.w;
        if (kc + GKC < K) {
            Ag += GKC; Bg += GKC;
            a0 = ldcg_f32x4(Ag);
            a1 = ldcg_f32x4(Ag + 4);
            b0 = ldcg_f32x4(Bg);
            b1 = ldcg_f32x4(Bg + 4);
        }
        __syncthreads();
        #pragma unroll
        for (int kk = 0; kk < GKC; ++kk) {
            ulonglong2 aa = *(const ulonglong2*)(&sA[kk][ty * 8]);
            ulonglong2 ab = *(const ulonglong2*)(&sA[kk][ty * 8 + 4]);
            float4 bv0 = *(const float4*)(&sB[kk][tx * 8]);
            float4 bv1 = *(const float4*)(&sB[kk][tx * 8 + 4]);
            float bs[8] = {bv0.x, bv0.y, bv0.z, bv0.w, bv1.x, bv1.y, bv1.z, bv1.w};
            #pragma unroll
            for (int c = 0; c < 8; ++c) {
                u64 bd = dup2(bs[c]);
                fma2(acc[0][c], aa.x, bd);
                fma2(acc[1][c], aa.y, bd);
                fma2(acc[2][c], ab.x, bd);
                fma2(acc[3][c], ab.y, bd);
            }
        }
        __syncthreads();
    }

    #pragma unroll
    for (int p = 0; p < 4; ++p) {
        float2 v[8];
        #pragma unroll
        for (int c = 0; c < 8; ++c) v[c] = unpk(acc[p][c]);
        int row0 = m0 + ty * 8 + p * 2;
        float* c0 = C + (size_t)row0 * N + n0 + tx * 8;
        float* c1 = c0 + N;
        *(float4*)(c0)     = make_float4(v[0].x, v[1].x, v[2].x, v[3].x);
        *(float4*)(c0 + 4) = make_float4(v[4].x, v[5].x, v[6].x, v[7].x);
        *(float4*)(c1)     = make_float4(v[0].y, v[1].y, v[2].y, v[3].y);
        *(float4*)(c1 + 4) = make_float4(v[4].y, v[5].y, v[6].y, v[7].y);
    }
}

// ============================================================================
// out[t,b,o] = h2[t,b,:] . w_lin[o,:] + b_lin[o]  (h2 in g_h1)
// ============================================================================
__global__ void __launch_bounds__(256)
out_linear(const float* __restrict__ w_lin, const float* __restrict__ b_lin,
           float* __restrict__ out)
{
    __shared__ float sA[16][68];
    __shared__ float sB[16][68];
    const int tid = threadIdx.x;
    const size_t rb = (size_t)blockIdx.x * 64;
    const int ty = tid >> 4;
    const int tx = tid & 15;
    const int li   = tid * 4;
    const int srow = li >> 4;
    const int skk  = li & 15;

    float acc[4][4] = {};

    for (int kc = 0; kc < HID; kc += 16) {
        __syncthreads();
        float4 va = ldcg_f32x4(g_h1 + (rb + srow) * HID + kc + skk);
        sA[skk + 0][srow] = va.x; sA[skk + 1][srow] = va.y;
        sA[skk + 2][srow] = va.z; sA[skk + 3][srow] = va.w;
        float4 vb = *(const float4*)(w_lin + (size_t)srow * HID + kc + skk);
        sB[skk + 0][srow] = vb.x; sB[skk + 1][srow] = vb.y;
        sB[skk + 2][srow] = vb.z; sB[skk + 3][srow] = vb.w;
        __syncthreads();
        #pragma unroll
        for (int kk = 0; kk < 16; ++kk) {
            float4 a = *(const float4*)&sA[kk][ty * 4];
            float4 b = *(const float4*)&sB[kk][tx * 4];
            acc[0][0] = fmaf(a.x, b.x, acc[0][0]); acc[0][1] = fmaf(a.x, b.y, acc[0][1]);
            acc[0][2] = fmaf(a.x, b.z, acc[0][2]); acc[0][3] = fmaf(a.x, b.w, acc[0][3]);
            acc[1][0] = fmaf(a.y, b.x, acc[1][0]); acc[1][1] = fmaf(a.y, b.y, acc[1][1]);
            acc[1][2] = fmaf(a.y, b.z, acc[1][2]); acc[1][3] = fmaf(a.y, b.w, acc[1][3]);
            acc[2][0] = fmaf(a.z, b.x, acc[2][0]); acc[2][1] = fmaf(a.z, b.y, acc[2][1]);
            acc[2][2] = fmaf(a.z, b.z, acc[2][2]); acc[2][3] = fmaf(a.z, b.w, acc[2][3]);
            acc[3][0] = fmaf(a.w, b.x, acc[3][0]); acc[3][1] = fmaf(a.w, b.y, acc[3][1]);
            acc[3][2] = fmaf(a.w, b.z, acc[3][2]); acc[3][3] = fmaf(a.w, b.w, acc[3][3]);
        }
    }

    #pragma unroll
    for (int i = 0; i < 4; ++i) {
        float4 o4;
        o4.x = acc[i][0] + b_lin[tx * 4 + 0];
        o4.y = acc[i][1] + b_lin[tx * 4 + 1];
        o4.z = acc[i][2] + b_lin[tx * 4 + 2];
        o4.w = acc[i][3] + b_lin[tx * 4 + 3];
        *(float4*)(out + (rb + ty * 4 + i) * OUT_DIM + tx * 4) = o4;
    }
}

extern "C" void kernel_launch(void* const* d_in, const int* in_sizes, int n_in,
                              void* d_out, int out_size)
{
    const float* x     = (const float*)d_in[0];
    const float* w_ih0 = (const float*)d_in[1];
    const float* w_hh0 = (const float*)d_in[2];
    const float* b_ih0 = (const float*)d_in[3];
    const float* b_hh0 = (const float*)d_in[4];
    const float* w_ih1 = (const float*)d_in[5];
    const float* w_hh1 = (const float*)d_in[6];
    const float* b_ih1 = (const float*)d_in[7];
    const float* b_hh1 = (const float*)d_in[8];
    const float* w_lin = (const float*)d_in[9];
    const float* b_lin = (const float*)d_in[10];
    float* out = (float*)d_out;
    (void)in_sizes; (void)n_in; (void)out_size;

    float *gi_ptr;
    cudaGetSymbolAddress((void**)&gi_ptr, g_gi);

    cudaFuncSetAttribute(gru_rec_mma, cudaFuncAttributeMaxDynamicSharedMemorySize, SMEM_TOT);
    cudaFuncSetAttribute(gemm_bf16_3s, cudaFuncAttributeMaxDynamicSharedMemorySize, 4 * GST);

    // w_ih1 transpose + split (independent of layer 0)
    conv_w<<<dim3(HID / 32, GATES / 32), 256>>>(w_ih1);

    // layer 0
    gemm_tn_f32x2<<<dim3(GATES / 128, MROWS / 128), 256>>>(x, w_ih0, gi_ptr,
                                                           MROWS, GATES, IN_DIM);
    gru_rec_mma<<<NBLK, RTHR, SMEM_TOT>>>(w_hh0, b_ih0, b_hh0);

    // layer 1
    gemm_bf16_3s<<<dim3(GATES / 128, MROWS / 128), 512, 4 * GST>>>(gi_ptr);
    gru_rec_mma<<<NBLK, RTHR, SMEM_TOT>>>(w_hh1, b_ih1, b_hh1);

    // time-distributed linear
    out_linear<<<MROWS / 64, 256>>>(w_lin, b_lin, out);
}

// round 9
// speedup vs baseline: 2.1631x; 1.0092x over previous
#include <cuda_runtime.h>
#include <cuda_bf16.h>
#include <math.h>
#include <stdint.h>

#define T_STEPS 512
#define BATCH   128
#define IN_DIM  64
#define HID     1024
#define OUT_DIM 64
#define GATES   (3 * HID)
#define MROWS   (T_STEPS * BATCH)   // 65536
#define NBLK    128
#define RTHR    512

typedef unsigned long long u64;

// Persistent scratch (device globals -- no allocation anywhere).
__device__ float g_gi[(size_t)MROWS * GATES];        // input-side gates
__device__ float g_h1[(size_t)MROWS * HID];          // layer outputs (fp32)
__device__ __nv_bfloat16 g_h1hi[(size_t)MROWS * HID];// layer outputs, bf16 hi plane
__device__ __nv_bfloat16 g_h1lo[(size_t)MROWS * HID];// layer outputs, bf16 lo plane
__device__ __nv_bfloat16 g_hzero[BATCH * HID];       // zeros (h_{-1})
__device__ __nv_bfloat16 g_wbhi[(size_t)HID * GATES];// w_ih1 transposed [k][n], hi
__device__ __nv_bfloat16 g_wblo[(size_t)HID * GATES];// lo
__device__ unsigned g_bar_gen;
__device__ unsigned g_bar_cnt;

// ---------- helpers ----------
__device__ __forceinline__ void fma2(u64 &d, u64 a, u64 b) {
    asm("fma.rn.f32x2 %0, %1, %2, %0;" : "+l"(d) : "l"(a), "l"(b));
}
__device__ __forceinline__ u64 dup2(float x) {
    u64 r; asm("mov.b64 %0, {%1, %1};" : "=l"(r) : "f"(x)); return r;
}
__device__ __forceinline__ float2 unpk(u64 v) {
    float2 r; asm("mov.b64 {%0, %1}, %2;" : "=f"(r.x), "=f"(r.y) : "l"(v)); return r;
}
__device__ __forceinline__ float4 ldcg_f32x4(const void* p) {
    float4 v;
    asm volatile("ld.global.cg.v4.f32 {%0, %1, %2, %3}, [%4];"
                 : "=f"(v.x), "=f"(v.y), "=f"(v.z), "=f"(v.w) : "l"(p));
    return v;
}
__device__ __forceinline__ float ldcg_f32(const void* p) {
    float v;
    asm volatile("ld.global.cg.f32 %0, [%1];" : "=f"(v) : "l"(p));
    return v;
}
__device__ __forceinline__ void cp16(unsigned d, const void* s) {
    asm volatile("cp.async.cg.shared.global [%0], [%1], 16;" :: "r"(d), "l"(s));
}
__device__ __forceinline__ void ldsm4(uint32_t* r, uint32_t a) {
    asm volatile("ldmatrix.sync.aligned.m8n8.x4.shared.b16 {%0,%1,%2,%3}, [%4];"
                 : "=r"(r[0]), "=r"(r[1]), "=r"(r[2]), "=r"(r[3]) : "r"(a));
}
__device__ __forceinline__ void ldsm2t(uint32_t* r, uint32_t a) {
    asm volatile("ldmatrix.sync.aligned.m8n8.x2.trans.shared.b16 {%0,%1}, [%2];"
                 : "=r"(r[0]), "=r"(r[1]) : "r"(a));
}
__device__ __forceinline__ void mma16816(float* c, const uint32_t* a, const uint32_t* b) {
    asm volatile("mma.sync.aligned.m16n8k16.row.col.f32.bf16.bf16.f32 "
                 "{%0,%1,%2,%3}, {%4,%5,%6,%7}, {%8,%9}, {%0,%1,%2,%3};"
                 : "+f"(c[0]), "+f"(c[1]), "+f"(c[2]), "+f"(c[3])
                 : "r"(a[0]), "r"(a[1]), "r"(a[2]), "r"(a[3]), "r"(b[0]), "r"(b[1]));
}
// swizzles (byte-offset XOR)
__device__ __forceinline__ uint32_t SWA(uint32_t a) { return a ^ ((a >> 3) & 0x10); }  // 32B rows
__device__ __forceinline__ uint32_t SWB(uint32_t a) { return a ^ ((a >> 3) & 0x30); }  // 64B rows
// 256B-row B tile: XOR the 16B-chunk column by (row&7)
__device__ __forceinline__ uint32_t SWR(int row, uint32_t c) { return c ^ (((uint32_t)row & 7u) << 4); }

// ---- cheap grid barrier: one fence + release/acquire, nanosleep poll ----
__device__ __forceinline__ void grid_bar() {
    __syncthreads();
    if (threadIdx.x == 0) {
        unsigned gen;
        asm volatile("ld.global.relaxed.gpu.u32 %0, [%1];"
                     : "=r"(gen) : "l"(&g_bar_gen));
        asm volatile("fence.acq_rel.gpu;" ::: "memory");   // release block's writes
        unsigned prev = atomicAdd(&g_bar_cnt, 1u);
        if (prev == (unsigned)(NBLK - 1)) {
            asm volatile("st.global.relaxed.gpu.u32 [%0], %1;"
                         :: "l"(&g_bar_cnt), "r"(0u) : "memory");
            asm volatile("fence.acq_rel.gpu;" ::: "memory");
            asm volatile("st.global.relaxed.gpu.u32 [%0], %1;"
                         :: "l"(&g_bar_gen), "r"(gen + 1u) : "memory");
        } else {
            unsigned cur;
            do {
                __nanosleep(64);
                asm volatile("ld.global.relaxed.gpu.u32 %0, [%1];"
                             : "=r"(cur) : "l"(&g_bar_gen));
            } while (cur == gen);
            asm volatile("fence.acq_rel.gpu;" ::: "memory"); // acquire releasers' writes
        }
    }
    __syncthreads();
}

// rec smem layout
#define SMEM_BIAS 0
#define SMEM_W    1024                   // W hi: [1024k][32n] bf16 SWB = 64 KB
#define SMEM_WLO  (1024 + 65536)
#define SMEM_ACT  (1024 + 131072)        // 16 warps x 3 bufs x 2 KB rings (red aliases)
#define SMEM_TOT  (SMEM_ACT + 98304)     // 230,400 B

// ============================================================================
// GRU recurrence on mma.sync; warp-private cp.async rings (no block syncs in
// k-loop). Warp (p=w&3, q=w>>2): m-rows [32p,32p+32) x n24 x k [256q,256q+256).
// ============================================================================
__global__ void __launch_bounds__(RTHR, 1)
gru_rec_mma(const float* __restrict__ w_hh, const float* __restrict__ b_ih,
            const float* __restrict__ b_hh)
{
    extern __shared__ char smem[];
    const int tid  = threadIdx.x;
    const int wid  = tid >> 5;
    const int lane = tid & 31;
    const int bid  = blockIdx.x;
    const int j0   = bid * 8;
    const int p    = wid & 3;
    const int q    = wid >> 2;
    const uint32_t sb = (uint32_t)__cvta_generic_to_shared(smem);

    // persistent W hi/lo: [k][n=gate*8+u] 64B rows, SWB
    for (int idx = tid; idx < 32 * HID; idx += RTHR) {
        int n = idx >> 10, k = idx & 1023;
        float w = 0.0f;
        if (n < 24) w = w_hh[((size_t)(n >> 3) * HID + j0 + (n & 7)) * HID + k];
        __nv_bfloat16 hi = __float2bfloat16(w);
        __nv_bfloat16 lo = __float2bfloat16(w - __bfloat162float(hi));
        uint32_t a = SWB((uint32_t)(k * 64 + n * 2));
        *(__nv_bfloat16*)(smem + SMEM_W   + a) = hi;
        *(__nv_bfloat16*)(smem + SMEM_WLO + a) = lo;
    }
    if (tid < 8) {
        float* sB = (float*)(smem + SMEM_BIAS);
        int j = j0 + tid;
        sB[tid]      = b_ih[j] + b_hh[j];
        sB[8 + tid]  = b_ih[HID + j] + b_hh[HID + j];
        sB[16 + tid] = b_ih[2 * HID + j];
        sB[24 + tid] = b_hh[2 * HID + j];
    }
    for (int idx = bid * RTHR + tid; idx < BATCH * HID; idx += NBLK * RTHR)
        g_hzero[idx] = __float2bfloat16(0.0f);
    __syncthreads();
    grid_bar();

    // lane-constant maps
    const int relrow = ((lane >> 3) & 1) * 8 + (lane & 7);
    const int segA   = lane >> 4;
    const uint32_t offA0 = SWA((uint32_t)(relrow * 32 + segA * 16));
    const uint32_t offA1 = SWA((uint32_t)((16 + relrow) * 32 + segA * 16));
    const int rbB = lane & 15;
    // warp-private staging: lane -> plane spl, rows r0, r0+1
    const int spl = lane >> 4;
    const int r0  = (lane & 15) * 2;
    const uint32_t ring0 = sb + SMEM_ACT + (uint32_t)(wid * 6144);
    const uint32_t d00 = (uint32_t)(spl * 1024) + SWA((uint32_t)(r0 * 32));
    const uint32_t d01 = (uint32_t)(spl * 1024) + SWA((uint32_t)(r0 * 32 + 16));
    const uint32_t d10 = (uint32_t)(spl * 1024) + SWA((uint32_t)((r0 + 1) * 32));
    const uint32_t d11 = (uint32_t)(spl * 1024) + SWA((uint32_t)((r0 + 1) * 32 + 16));
    const int eu = tid & 7;
    const int em = tid >> 3;

    for (int t = 0; t < T_STEPS; ++t) {
        const __nv_bfloat16* hi_src = t ? g_h1hi + (size_t)(t - 1) * BATCH * HID : g_hzero;
        const __nv_bfloat16* lo_src = t ? g_h1lo + (size_t)(t - 1) * BATCH * HID : g_hzero;
        const __nv_bfloat16* sp = (spl ? lo_src : hi_src)
                                + (size_t)(32 * p + r0) * HID + q * 256;

        // prologue: stage chunks 0,1 into ring bufs 0,1
        #pragma unroll
        for (int pre = 0; pre < 2; ++pre) {
            uint32_t base = ring0 + (uint32_t)(pre * 2048);
            const __nv_bfloat16* s = sp + pre * 16;
            cp16(base + d00, s);       cp16(base + d01, s + 8);
            cp16(base + d10, s + HID); cp16(base + d11, s + HID + 8);
            asm volatile("cp.async.commit_group;");
        }

        // epilogue operand prefetch
        float gir[2], giz[2], gin[2], hpv[2];
        #pragma unroll
        for (int it = 0; it < 2; ++it) {
            int m = em + it * 64;
            const float* gp = g_gi + ((size_t)t * BATCH + m) * GATES + j0 + eu;
            gir[it] = ldcg_f32(gp);
            giz[it] = ldcg_f32(gp + HID);
            gin[it] = ldcg_f32(gp + 2 * HID);
            hpv[it] = t ? ldcg_f32(g_h1 + ((size_t)(t - 1) * BATCH + m) * HID + j0 + eu)
                        : 0.0f;
        }

        float c[2][3][4];
        #pragma unroll
        for (int mt = 0; mt < 2; ++mt)
            #pragma unroll
            for (int g = 0; g < 3; ++g)
                #pragma unroll
                for (int r = 0; r < 4; ++r) c[mt][g][r] = 0.0f;

        #pragma unroll 1
        for (int i = 0; i < 16; ++i) {
            if (i + 2 < 16) {
                uint32_t base = ring0 + (uint32_t)(((i + 2) % 3) * 2048);
                const __nv_bfloat16* s = sp + (i + 2) * 16;
                cp16(base + d00, s);       cp16(base + d01, s + 8);
                cp16(base + d10, s + HID); cp16(base + d11, s + HID + 8);
                asm volatile("cp.async.commit_group;");
                asm volatile("cp.async.wait_group 2;");
            } else if (i == 14) {
                asm volatile("cp.async.wait_group 1;");
            } else {
                asm volatile("cp.async.wait_group 0;");
            }
            __syncwarp();

            const int kb = q * 256 + i * 16;
            const uint32_t bbase = (uint32_t)((kb + rbB) * 64);
            uint32_t bh[3][2], bl[3][2];
            #pragma unroll
            for (int g = 0; g < 3; ++g) {
                uint32_t a = SWB(bbase + (uint32_t)(g * 16));
                ldsm2t(bh[g], sb + SMEM_W + a);
                ldsm2t(bl[g], sb + SMEM_WLO + a);
            }
            const uint32_t abase = ring0 + (uint32_t)((i % 3) * 2048);
            #pragma unroll
            for (int mt = 0; mt < 2; ++mt) {
                uint32_t off = mt ? offA1 : offA0;
                uint32_t ah[4], al[4];
                ldsm4(ah, abase + off);
                ldsm4(al, abase + 1024 + off);
                #pragma unroll
                for (int g = 0; g < 3; ++g) {
                    mma16816(c[mt][g], ah, bh[g]);
                    mma16816(c[mt][g], al, bh[g]);
                    mma16816(c[mt][g], ah, bl[g]);
                }
            }
        }

        __syncthreads();   // rings idle; red aliases them
        float* red = (float*)(smem + SMEM_ACT);   // [128 m][24 n][4 q]
        {
            const int rr0 = p * 32 + (lane >> 2);
            const int c2  = (lane & 3) * 2;
            #pragma unroll
            for (int mt = 0; mt < 2; ++mt) {
                int rr = rr0 + mt * 16;
                #pragma unroll
                for (int g = 0; g < 3; ++g) {
                    int nn = g * 8 + c2;
                    red[(rr * 24 + nn) * 4 + q]           = c[mt][g][0];
                    red[(rr * 24 + nn + 1) * 4 + q]       = c[mt][g][1];
                    red[((rr + 8) * 24 + nn) * 4 + q]     = c[mt][g][2];
                    red[((rr + 8) * 24 + nn + 1) * 4 + q] = c[mt][g][3];
                }
            }
        }
        __syncthreads();

        {
            const float* sB = (const float*)(smem + SMEM_BIAS);
            #pragma unroll
            for (int it = 0; it < 2; ++it) {
                int m = em + it * 64;
                float4 vr = *(const float4*)(red + ((size_t)m * 24 + eu) * 4);
                float4 vz = *(const float4*)(red + ((size_t)m * 24 + 8 + eu) * 4);
                float4 vn = *(const float4*)(red + ((size_t)m * 24 + 16 + eu) * 4);
                float ghr = (vr.x + vr.y) + (vr.z + vr.w);
                float ghz = (vz.x + vz.y) + (vz.z + vz.w);
                float ghn = (vn.x + vn.y) + (vn.z + vn.w);
                float rg = 1.0f / (1.0f + expf(-(gir[it] + ghr + sB[eu])));
                float zg = 1.0f / (1.0f + expf(-(giz[it] + ghz + sB[8 + eu])));
                float ng = tanhf(gin[it] + sB[16 + eu] + rg * (ghn + sB[24 + eu]));
                float h  = (1.0f - zg) * ng + zg * hpv[it];

                __nv_bfloat16 hi = __float2bfloat16(h);
                __nv_bfloat16 lo = __float2bfloat16(h - __bfloat162float(hi));
                size_t o = ((size_t)t * BATCH + m) * HID + j0 + eu;
                g_h1hi[o] = hi;
                g_h1lo[o] = lo;
                g_h1[o]   = h;
            }
        }

        grid_bar();
    }
}

// ============================================================================
// Transpose + bf16-split w_ih1: [3072 n][1024 k] fp32 -> [k][n] hi/lo planes.
// ============================================================================
__global__ void __launch_bounds__(256)
conv_w(const float* __restrict__ w)
{
    __shared__ float tile[32][33];
    const int tx = threadIdx.x & 31;
    const int ty = threadIdx.x >> 5;       // 0..7
    const int k0 = blockIdx.x * 32;
    const int n0 = blockIdx.y * 32;
    #pragma unroll
    for (int r = 0; r < 4; ++r)
        tile[ty + r * 8][tx] = w[(size_t)(n0 + ty + r * 8) * HID + k0 + tx];
    __syncthreads();
    #pragma unroll
    for (int r = 0; r < 4; ++r) {
        float v = tile[tx][ty + r * 8];
        __nv_bfloat16 hi = __float2bfloat16(v);
        __nv_bfloat16 lo = __float2bfloat16(v - __bfloat162float(hi));
        size_t o = (size_t)(k0 + ty + r * 8) * GATES + n0 + tx;
        g_wbhi[o] = hi;
        g_wblo[o] = lo;
    }
}

// ============================================================================
// gi1 = h1 @ w_ih1^T on mma.sync (bf16 3-split). Tile 128m x 128n, K=1024.
// Stage = A[2pl][128m][32B] (8KB, SWA) + B[2pl][16k][256B] (8KB, SWR) = 16KB.
// 4-deep ring in dynamic smem (64 KB). 512 thr: tid<256 stage A, >=256 stage B.
// ============================================================================
#define GST 16384
__global__ void __launch_bounds__(512)
gemm_bf16_3s(float* __restrict__ C)
{
    extern __shared__ char gsm[];   // 4 * 16384
    const int tid  = threadIdx.x;
    const int wid  = tid >> 5;
    const int lane = tid & 31;
    const int m0 = blockIdx.y * 128;
    const int n0 = blockIdx.x * 128;
    const int p  = wid & 3;
    const int nq = wid >> 2;
    const uint32_t sb = (uint32_t)__cvta_generic_to_shared(gsm);

    const int relrow = ((lane >> 3) & 1) * 8 + (lane & 7);
    const int segA   = lane >> 4;
    const uint32_t offA0 = SWA((uint32_t)((p * 32 + relrow) * 32 + segA * 16));
    const uint32_t offA1 = SWA((uint32_t)((p * 32 + 16 + relrow) * 32 + segA * 16));
    const int rbB = lane & 15;
    uint32_t offB[4];
    #pragma unroll
    for (int nt = 0; nt < 4; ++nt)
        offB[nt] = (uint32_t)(8192 + rbB * 256) + SWR(rbB, (uint32_t)(nq * 64 + nt * 16));

    // staging maps
    const bool stA = (tid < 256);
    const int  apl = (tid >> 7) & 1;        // A plane
    const int  am  = tid & 127;             // A m-row
    const int  bix = tid & 255;             // for tid>=256: 0..255
    const int  bpl = bix >> 7;              // B plane
    const int  brw = (bix & 127) >> 3;      // B k-row 0..15
    const int  bcs = (bix & 7) * 32;        // B col byte 0..224

    const __nv_bfloat16* Asrc = (apl ? g_h1lo : g_h1hi) + (size_t)(m0 + am) * HID;
    const __nv_bfloat16* Bpl  = (bpl ? g_wblo : g_wbhi) + n0 + bcs / 2;
    const uint32_t adst0 = (uint32_t)(apl * 4096) + SWA((uint32_t)(am * 32));
    const uint32_t adst1 = (uint32_t)(apl * 4096) + SWA((uint32_t)(am * 32 + 16));
    const uint32_t bdst0 = (uint32_t)(8192 + bpl * 4096 + brw * 256)
                         + SWR(brw, (uint32_t)bcs);
    const uint32_t bdst1 = (uint32_t)(8192 + bpl * 4096 + brw * 256)
                         + SWR(brw, (uint32_t)(bcs + 16));

    float c[2][4][4];
    #pragma unroll
    for (int mt = 0; mt < 2; ++mt)
        #pragma unroll
        for (int nt = 0; nt < 4; ++nt)
            #pragma unroll
            for (int r = 0; r < 4; ++r) c[mt][nt][r] = 0.0f;

    // prologue: stage chunks 0,1,2
    #pragma unroll
    for (int pre = 0; pre < 3; ++pre) {
        uint32_t base = sb + (uint32_t)(pre * GST);
        if (stA) {
            cp16(base + adst0, Asrc + pre * 16);
            cp16(base + adst1, Asrc + pre * 16 + 8);
        } else {
            const __nv_bfloat16* s = Bpl + (size_t)(pre * 16 + brw) * GATES;
            cp16(base + bdst0, s);
            cp16(base + bdst1, s + 8);
        }
        asm volatile("cp.async.commit_group;");
    }

    #pragma unroll 1
    for (int i = 0; i < 64; ++i) {
        __syncthreads();
        if (i + 3 < 64) {
            uint32_t base = sb + (uint32_t)(((i + 3) & 3) * GST);
            if (stA) {
                cp16(base + adst0, Asrc + (i + 3) * 16);
                cp16(base + adst1, Asrc + (i + 3) * 16 + 8);
            } else {
                const __nv_bfloat16* s = Bpl + (size_t)((i + 3) * 16 + brw) * GATES;
                cp16(base + bdst0, s);
                cp16(base + bdst1, s + 8);
            }
            asm volatile("cp.async.commit_group;");
            asm volatile("cp.async.wait_group 3;");
        } else {
            asm volatile("cp.async.wait_group 0;");
        }
        __syncthreads();

        const uint32_t base = sb + (uint32_t)((i & 3) * GST);
        uint32_t bh[4][2], bl[4][2];
        #pragma unroll
        for (int nt = 0; nt < 4; ++nt) {
            ldsm2t(bh[nt], base + offB[nt]);
            ldsm2t(bl[nt], base + offB[nt] + 4096);
        }
        #pragma unroll
        for (int mt = 0; mt < 2; ++mt) {
            uint32_t off = mt ? offA1 : offA0;
            uint32_t ah[4], al[4];
            ldsm4(ah, base + off);
            ldsm4(al, base + 4096 + off);
            #pragma unroll
            for (int nt = 0; nt < 4; ++nt) {
                mma16816(c[mt][nt], ah, bh[nt]);
                mma16816(c[mt][nt], al, bh[nt]);
                mma16816(c[mt][nt], ah, bl[nt]);
            }
        }
    }

    // writeback
    #pragma unroll
    for (int mt = 0; mt < 2; ++mt) {
        int row = m0 + p * 32 + mt * 16 + (lane >> 2);
        #pragma unroll
        for (int nt = 0; nt < 4; ++nt) {
            int col = n0 + nq * 32 + nt * 8 + (lane & 3) * 2;
            *(float2*)(C + (size_t)row * GATES + col) =
                make_float2(c[mt][nt][0], c[mt][nt][1]);
            *(float2*)(C + (size_t)(row + 8) * GATES + col) =
                make_float2(c[mt][nt][2], c[mt][nt][3]);
        }
    }
}

// ============================================================================
// gi0 = x @ w_ih0^T  (K=64, fp32 f32x2)
// ============================================================================
#define GKC 16
__global__ void __launch_bounds__(256)
gemm_tn_f32x2(const float* __restrict__ A, const float* __restrict__ B,
              float* __restrict__ C, int M, int N, int K)
{
    __shared__ float sA[GKC][132];
    __shared__ float sB[GKC][132];
    const int tid = threadIdx.x;
    const int m0  = blockIdx.y * 128;
    const int n0  = blockIdx.x * 128;
    const int ty  = tid >> 4, tx = tid & 15;
    const int sr = tid >> 1;
    const int sk = (tid & 1) * 8;

    u64 acc[4][8];
    #pragma unroll
    for (int p = 0; p < 4; ++p)
        #pragma unroll
        for (int c = 0; c < 8; ++c) acc[p][c] = 0ull;

    const float* Ag = A + (size_t)(m0 + sr) * K + sk;
    const float* Bg = B + (size_t)(n0 + sr) * K + sk;
    float4 a0 = ldcg_f32x4(Ag);
    float4 a1 = ldcg_f32x4(Ag + 4);
    float4 b0 = ldcg_f32x4(Bg);
    float4 b1 = ldcg_f32x4(Bg + 4);

    for (int kc = 0; kc < K; kc += GKC) {
        sA[sk + 0][sr] = a0.x; sA[sk + 1][sr] = a0.y;
        sA[sk + 2][sr] = a0.z; sA[sk + 3][sr] = a0.w;
        sA[sk + 4][sr] = a1.x; sA[sk + 5][sr] = a1.y;
        sA[sk + 6][sr] = a1.z; sA[sk + 7][sr] = a1.w;
        sB[sk + 0][sr] = b0.x; sB[sk + 1][sr] = b0.y;
        sB[sk + 2][sr] = b0.z; sB[sk + 3][sr] = b0.w;
        sB[sk + 4][sr] = b1.x; sB[sk + 5][sr] = b1.y;
        sB[sk + 6][sr] = b1.z; sB[sk + 7][sr] = b1.w;
        if (kc + GKC < K) {
            Ag += GKC; Bg += GKC;
            a0 = ldcg_f32x4(Ag);
            a1 = ldcg_f32x4(Ag + 4);
            b0 = ldcg_f32x4(Bg);
            b1 = ldcg_f32x4(Bg + 4);
        }
        __syncthreads();
        #pragma unroll
        for (int kk = 0; kk < GKC; ++kk) {
            ulonglong2 aa = *(const ulonglong2*)(&sA[kk][ty * 8]);
            ulonglong2 ab = *(const ulonglong2*)(&sA[kk][ty * 8 + 4]);
            float4 bv0 = *(const float4*)(&sB[kk][tx * 8]);
            float4 bv1 = *(const float4*)(&sB[kk][tx * 8 + 4]);
            float bs[8] = {bv0.x, bv0.y, bv0.z, bv0.w, bv1.x, bv1.y, bv1.z, bv1.w};
            #pragma unroll
            for (int c = 0; c < 8; ++c) {
                u64 bd = dup2(bs[c]);
                fma2(acc[0][c], aa.x, bd);
                fma2(acc[1][c], aa.y, bd);
                fma2(acc[2][c], ab.x, bd);
                fma2(acc[3][c], ab.y, bd);
            }
        }
        __syncthreads();
    }

    #pragma unroll
    for (int p = 0; p < 4; ++p) {
        float2 v[8];
        #pragma unroll
        for (int c = 0; c < 8; ++c) v[c] = unpk(acc[p][c]);
        int row0 = m0 + ty * 8 + p * 2;
        float* c0 = C + (size_t)row0 * N + n0 + tx * 8;
        float* c1 = c0 + N;
        *(float4*)(c0)     = make_float4(v[0].x, v[1].x, v[2].x, v[3].x);
        *(float4*)(c0 + 4) = make_float4(v[4].x, v[5].x, v[6].x, v[7].x);
        *(float4*)(c1)     = make_float4(v[0].y, v[1].y, v[2].y, v[3].y);
        *(float4*)(c1 + 4) = make_float4(v[4].y, v[5].y, v[6].y, v[7].y);
    }
}

// ============================================================================
// out[t,b,o] = h2[t,b,:] . w_lin[o,:] + b_lin[o]  (h2 in g_h1)
// ============================================================================
__global__ void __launch_bounds__(256)
out_linear(const float* __restrict__ w_lin, const float* __restrict__ b_lin,
           float* __restrict__ out)
{
    __shared__ float sA[16][68];
    __shared__ float sB[16][68];
    const int tid = threadIdx.x;
    const size_t rb = (size_t)blockIdx.x * 64;
    const int ty = tid >> 4;
    const int tx = tid & 15;
    const int li   = tid * 4;
    const int srow = li >> 4;
    const int skk  = li & 15;

    float acc[4][4] = {};

    for (int kc = 0; kc < HID; kc += 16) {
        __syncthreads();
        float4 va = ldcg_f32x4(g_h1 + (rb + srow) * HID + kc + skk);
        sA[skk + 0][srow] = va.x; sA[skk + 1][srow] = va.y;
        sA[skk + 2][srow] = va.z; sA[skk + 3][srow] = va.w;
        float4 vb = *(const float4*)(w_lin + (size_t)srow * HID + kc + skk);
        sB[skk + 0][srow] = vb.x; sB[skk + 1][srow] = vb.y;
        sB[skk + 2][srow] = vb.z; sB[skk + 3][srow] = vb.w;
        __syncthreads();
        #pragma unroll
        for (int kk = 0; kk < 16; ++kk) {
            float4 a = *(const float4*)&sA[kk][ty * 4];
            float4 b = *(const float4*)&sB[kk][tx * 4];
            acc[0][0] = fmaf(a.x, b.x, acc[0][0]); acc[0][1] = fmaf(a.x, b.y, acc[0][1]);
            acc[0][2] = fmaf(a.x, b.z, acc[0][2]); acc[0][3] = fmaf(a.x, b.w, acc[0][3]);
            acc[1][0] = fmaf(a.y, b.x, acc[1][0]); acc[1][1] = fmaf(a.y, b.y, acc[1][1]);
            acc[1][2] = fmaf(a.y, b.z, acc[1][2]); acc[1][3] = fmaf(a.y, b.w, acc[1][3]);
            acc[2][0] = fmaf(a.z, b.x, acc[2][0]); acc[2][1] = fmaf(a.z, b.y, acc[2][1]);
            acc[2][2] = fmaf(a.z, b.z, acc[2][2]); acc[2][3] = fmaf(a.z, b.w, acc[2][3]);
            acc[3][0] = fmaf(a.w, b.x, acc[3][0]); acc[3][1] = fmaf(a.w, b.y, acc[3][1]);
            acc[3][2] = fmaf(a.w, b.z, acc[3][2]); acc[3][3] = fmaf(a.w, b.w, acc[3][3]);
        }
    }

    #pragma unroll
    for (int i = 0; i < 4; ++i) {
        float4 o4;
        o4.x = acc[i][0] + b_lin[tx * 4 + 0];
        o4.y = acc[i][1] + b_lin[tx * 4 + 1];
        o4.z = acc[i][2] + b_lin[tx * 4 + 2];
        o4.w = acc[i][3] + b_lin[tx * 4 + 3];
        *(float4*)(out + (rb + ty * 4 + i) * OUT_DIM + tx * 4) = o4;
    }
}

extern "C" void kernel_launch(void* const* d_in, const int* in_sizes, int n_in,
                              void* d_out, int out_size)
{
    const float* x     = (const float*)d_in[0];
    const float* w_ih0 = (const float*)d_in[1];
    const float* w_hh0 = (const float*)d_in[2];
    const float* b_ih0 = (const float*)d_in[3];
    const float* b_hh0 = (const float*)d_in[4];
    const float* w_ih1 = (const float*)d_in[5];
    const float* w_hh1 = (const float*)d_in[6];
    const float* b_ih1 = (const float*)d_in[7];
    const float* b_hh1 = (const float*)d_in[8];
    const float* w_lin = (const float*)d_in[9];
    const float* b_lin = (const float*)d_in[10];
    float* out = (float*)d_out;
    (void)in_sizes; (void)n_in; (void)out_size;

    float *gi_ptr;
    cudaGetSymbolAddress((void**)&gi_ptr, g_gi);

    cudaFuncSetAttribute(gru_rec_mma, cudaFuncAttributeMaxDynamicSharedMemorySize, SMEM_TOT);
    cudaFuncSetAttribute(gemm_bf16_3s, cudaFuncAttributeMaxDynamicSharedMemorySize, 4 * GST);

    // w_ih1 transpose + split (independent of layer 0)
    conv_w<<<dim3(HID / 32, GATES / 32), 256>>>(w_ih1);

    // layer 0
    gemm_tn_f32x2<<<dim3(GATES / 128, MROWS / 128), 256>>>(x, w_ih0, gi_ptr,
                                                           MROWS, GATES, IN_DIM);
    gru_rec_mma<<<NBLK, RTHR, SMEM_TOT>>>(w_hh0, b_ih0, b_hh0);

    // layer 1
    gemm_bf16_3s<<<dim3(GATES / 128, MROWS / 128), 512, 4 * GST>>>(gi_ptr);
    gru_rec_mma<<<NBLK, RTHR, SMEM_TOT>>>(w_hh1, b_ih1, b_hh1);

    // time-distributed linear
    out_linear<<<MROWS / 64, 256>>>(w_lin, b_lin, out);
}